// round 10
// baseline (speedup 1.0000x reference)
#include <cuda_runtime.h>
#include <cuda_bf16.h>
#include <math.h>
#include <stdint.h>

typedef __nv_bfloat16 bf16;

// ---------------- problem constants ----------------
#define NQd 1000
#define BSd 4
#define Cd 256
#define NHd 8
#define HDd 32
#define NVd 20000
#define Wb 100
#define Hb 200
#define FFNd 512
#define M4 4000            // BS*NQ
#define EPSd 1e-5f

// ---------------- scratch (single device symbol, partitioned on host) ----
__device__ __align__(256) float g_scratch[70000000];

// ================= helpers =========================
__device__ __forceinline__ uint32_t smem_u32(const void* p) {
    return (uint32_t)__cvta_generic_to_shared(p);
}
__device__ __forceinline__ void cp16(uint32_t s, const void* g, int sz) {
    asm volatile("cp.async.cg.shared.global [%0], [%1], 16, %2;\n"
                 :: "r"(s), "l"(g), "r"(sz));
}
__device__ __forceinline__ void mma16816(float* d, const uint32_t* a, const uint32_t* b) {
    asm volatile(
        "mma.sync.aligned.m16n8k16.row.col.f32.bf16.bf16.f32 "
        "{%0,%1,%2,%3}, {%4,%5,%6,%7}, {%8,%9}, {%0,%1,%2,%3};\n"
        : "+f"(d[0]), "+f"(d[1]), "+f"(d[2]), "+f"(d[3])
        : "r"(a[0]), "r"(a[1]), "r"(a[2]), "r"(a[3]), "r"(b[0]), "r"(b[1]));
}
__device__ __forceinline__ void split_write(bf16* H, bf16* L, long long off, float x) {
    bf16 h = __float2bfloat16(x);
    H[off] = h;
    L[off] = __float2bfloat16(x - __bfloat162float(h));
}
__device__ __forceinline__ uint32_t pack_bf2(float a, float b) {
    __nv_bfloat162 t = __floats2bfloat162_rn(a, b);
    return *(uint32_t*)&t;
}

// ================= pipelined bf16x3 tensor-core GEMM =====================
// 3-stage cp.async ring, ONE __syncthreads per k-block.
// C[m][n] = alpha * sum_k A[m][k]*B[n][k] + bias[n]; A,B as hi/lo planes.
template<int BM, int BN, int WM, int WN>
__global__ void __launch_bounds__((BM/WM)*(BN/WN)*32) bf_gemm(
    int M, int N, int K,
    const bf16* __restrict__ Ah, const bf16* __restrict__ Al, int sA,
    long long strA1, long long strA2,
    const bf16* __restrict__ Bh, const bf16* __restrict__ Bl, int sB,
    long long strB1, long long strB2,
    float* Cf, bf16* Ch, bf16* Cl, int ldc, long long strC1, long long strC2,
    const float* __restrict__ bias, float alpha, int relu, int batch2)
{
    constexpr int BK = 32;
    constexpr int NST = 3;
    constexpr int WARPS_M = BM / WM;
    constexpr int WARPS_N = BN / WN;
    constexpr int NT = WARPS_M * WARPS_N * 32;
    constexpr int LDA = 40;
    constexpr int MT = WM / 16;
    constexpr int NTn = WN / 8;
    constexpr int PA = BM * LDA;
    constexpr int PB = BN * LDA;
    constexpr int STAGE = 2 * PA + 2 * PB;
    constexpr int CA = BM * 4;
    constexpr int CT = (BM + BN) * 4;

    extern __shared__ __align__(16) bf16 sm[];

    int z = blockIdx.z;
    int i1 = z / batch2, i2 = z - i1 * batch2;
    Ah += i1 * strA1 + i2 * strA2;  Al += i1 * strA1 + i2 * strA2;
    Bh += i1 * strB1 + i2 * strB2;  Bl += i1 * strB1 + i2 * strB2;
    long long coff = i1 * strC1 + i2 * strC2;

    int m0 = blockIdx.x * BM;
    int n0 = blockIdx.y * BN;
    int tid = threadIdx.x, lane = tid & 31, warp = tid >> 5;
    int wm = warp / WARPS_N, wn = warp - wm * WARPS_N;
    int lr = lane >> 2, lc = (lane & 3) << 1;

    float acc[MT][NTn][4];
#pragma unroll
    for (int i = 0; i < MT; i++)
#pragma unroll
        for (int j = 0; j < NTn; j++)
#pragma unroll
            for (int c = 0; c < 4; c++) acc[i][j][c] = 0.f;

    int nkb = (K + BK - 1) / BK;

    auto load_stage = [&](int st, int k0) {
        bf16* basep = sm + st * STAGE;
        for (int c = tid; c < CT; c += NT) {
            if (c < CA) {
                int row = c >> 2, kc = (c & 3) << 3;
                int m = m0 + row, k = k0 + kc;
                int sz = 0;
                int mc = (m < M) ? m : (M - 1);
                int kcl = (k < K) ? k : 0;
                if (m < M && k < K) { sz = (K - k) * 2; if (sz > 16) sz = 16; }
                long long go = (long long)mc * sA + kcl;
                uint32_t s0 = smem_u32(basep + row * LDA + kc);
                cp16(s0, Ah + go, sz);
                cp16(s0 + PA * 2, Al + go, sz);
            } else {
                int cc = c - CA;
                int row = cc >> 2, kc = (cc & 3) << 3;
                int n = n0 + row, k = k0 + kc;
                int sz = 0;
                int nc = (n < N) ? n : (N - 1);
                int kcl = (k < K) ? k : 0;
                if (n < N && k < K) { sz = (K - k) * 2; if (sz > 16) sz = 16; }
                long long go = (long long)nc * sB + kcl;
                uint32_t s0 = smem_u32(basep + 2 * PA + row * LDA + kc);
                cp16(s0, Bh + go, sz);
                cp16(s0 + PB * 2, Bl + go, sz);
            }
        }
    };

    auto compute = [&](int st) {
        bf16* Ahs = sm + st * STAGE;
        bf16* Als = Ahs + PA;
        bf16* Bhs = Ahs + 2 * PA;
        bf16* Bls = Bhs + PB;
#pragma unroll
        for (int ks = 0; ks < BK; ks += 16) {
            uint32_t af[MT][4], bhf[NTn][2], blf[NTn][2];
#pragma unroll
            for (int i = 0; i < MT; i++) {
                int row = wm * WM + i * 16 + lr;
                af[i][0] = *(const uint32_t*)(Ahs + (row    ) * LDA + ks + lc);
                af[i][1] = *(const uint32_t*)(Ahs + (row + 8) * LDA + ks + lc);
                af[i][2] = *(const uint32_t*)(Ahs + (row    ) * LDA + ks + lc + 8);
                af[i][3] = *(const uint32_t*)(Ahs + (row + 8) * LDA + ks + lc + 8);
            }
#pragma unroll
            for (int j = 0; j < NTn; j++) {
                int brow = wn * WN + j * 8 + lr;
                bhf[j][0] = *(const uint32_t*)(Bhs + brow * LDA + ks + lc);
                bhf[j][1] = *(const uint32_t*)(Bhs + brow * LDA + ks + lc + 8);
                blf[j][0] = *(const uint32_t*)(Bls + brow * LDA + ks + lc);
                blf[j][1] = *(const uint32_t*)(Bls + brow * LDA + ks + lc + 8);
            }
#pragma unroll
            for (int i = 0; i < MT; i++)
#pragma unroll
                for (int j = 0; j < NTn; j++) {
                    mma16816(acc[i][j], af[i], bhf[j]);   // hi*hi
                    mma16816(acc[i][j], af[i], blf[j]);   // hi*lo
                }
#pragma unroll
            for (int i = 0; i < MT; i++) {
                int row = wm * WM + i * 16 + lr;
                af[i][0] = *(const uint32_t*)(Als + (row    ) * LDA + ks + lc);
                af[i][1] = *(const uint32_t*)(Als + (row + 8) * LDA + ks + lc);
                af[i][2] = *(const uint32_t*)(Als + (row    ) * LDA + ks + lc + 8);
                af[i][3] = *(const uint32_t*)(Als + (row + 8) * LDA + ks + lc + 8);
            }
#pragma unroll
            for (int i = 0; i < MT; i++)
#pragma unroll
                for (int j = 0; j < NTn; j++)
                    mma16816(acc[i][j], af[i], bhf[j]);   // lo*hi
        }
    };

    // 3-stage ring: prefetch 2 stages, single barrier per iteration.
    load_stage(0, 0);
    asm volatile("cp.async.commit_group;\n");
    if (nkb > 1) {
        load_stage(1, BK);
        asm volatile("cp.async.commit_group;\n");
    }
    for (int kb = 0; kb < nkb; kb++) {
        if (kb + 1 < nkb) asm volatile("cp.async.wait_group 1;\n");
        else              asm volatile("cp.async.wait_group 0;\n");
        __syncthreads();
        compute(kb % NST);
        if (kb + 2 < nkb) {
            load_stage((kb + 2) % NST, (kb + 2) * BK);
            asm volatile("cp.async.commit_group;\n");
        }
    }

    float* Cfp = Cf ? Cf + coff : nullptr;
    bf16* Chp = Ch ? Ch + coff : nullptr;
    bf16* Clp = Cl ? Cl + coff : nullptr;
#pragma unroll
    for (int i = 0; i < MT; i++) {
        int row0 = m0 + wm * WM + i * 16 + lr;
#pragma unroll
        for (int j = 0; j < NTn; j++) {
            int col0 = n0 + wn * WN + j * 8 + lc;
#pragma unroll
            for (int c = 0; c < 4; c++) {
                int m = row0 + ((c >> 1) << 3);
                int n = col0 + (c & 1);
                if (m < M && n < N) {
                    float vv = acc[i][j][c] * alpha;
                    if (bias) vv += bias[n];
                    if (relu) vv = fmaxf(vv, 0.f);
                    long long o = (long long)m * ldc + n;
                    if (Cfp) Cfp[o] = vv;
                    if (Chp) {
                        bf16 hh = __float2bfloat16(vv);
                        Chp[o] = hh;
                        Clp[o] = __float2bfloat16(vv - __bfloat162float(hh));
                    }
                }
            }
        }
    }
}

// ================= flash attention (bf16x3, online softmax) ==============
__global__ void __launch_bounds__(256) flash_kernel(
    const bf16* __restrict__ qkvh, const bf16* __restrict__ qkvl,
    const bf16* __restrict__ vTh,  const bf16* __restrict__ vTl,
    bf16* __restrict__ aoh, bf16* __restrict__ aol)
{
    constexpr int LKV = 64;
    constexpr int LDQ = 40, LDV = 72;
    constexpr int QPA = 128 * LDQ;
    constexpr int KPA = LKV * LDQ;
    constexpr int VPA = 32 * LDV;
    constexpr int KVSTAGE = 2 * KPA + 2 * VPA;

    extern __shared__ __align__(16) bf16 smf[];
    bf16* Qh = smf;
    bf16* Ql = smf + QPA;
    bf16* STG = smf + 2 * QPA;

    int bz = blockIdx.y;
    int b = bz >> 3, h = bz & 7;
    int q0 = blockIdx.x * 128;
    int tid = threadIdx.x, lane = tid & 31, w = tid >> 5;
    int lr = lane >> 2, lc = (lane & 3) << 1;

    const bf16* qbase_h = qkvh + (long long)b * NQd * 768 + h * 32;
    const bf16* qbase_l = qkvl + (long long)b * NQd * 768 + h * 32;
    const bf16* vbase_h = vTh + (long long)bz * (HDd * NQd);
    const bf16* vbase_l = vTl + (long long)bz * (HDd * NQd);

    for (int c = tid; c < 1024; c += 256) {
        int plane = c >> 9, rem = c & 511;
        int row = rem >> 2, kc = (rem & 3) << 3;
        int q = q0 + row;
        int qm = (q < NQd) ? q : (NQd - 1);
        int sz = (q < NQd) ? 16 : 0;
        const bf16* src = (plane ? qbase_l : qbase_h) + (long long)qm * 768 + kc;
        uint32_t dst = smem_u32((plane ? Ql : Qh) + row * LDQ + kc);
        cp16(dst, src, sz);
    }

    auto load_kv = [&](int st, int kv0) {
        bf16* Kh = STG + st * KVSTAGE;
        bf16* Kl = Kh + KPA;
        bf16* Vh = Kl + KPA;
        bf16* Vl = Vh + VPA;
        for (int c = tid; c < 512; c += 256) {
            int plane = c >> 8, rem = c & 255;
            int row = rem >> 2, kc = (rem & 3) << 3;
            int kv = kv0 + row;
            int kvm = (kv < NQd) ? kv : (NQd - 1);
            int sz = (kv < NQd) ? 16 : 0;
            const bf16* src = (plane ? qbase_l : qbase_h) + (long long)kvm * 768 + 256 + kc;
            uint32_t dst = smem_u32((plane ? Kl : Kh) + row * LDQ + kc);
            cp16(dst, src, sz);
        }
        for (int c = tid; c < 512; c += 256) {
            int plane = c >> 8, rem = c & 255;
            int d = rem >> 3, cc = (rem & 7) << 3;
            int col = kv0 + cc;
            int colm = (col < NQd) ? col : (NQd - 8);
            int sz = (NQd - col) * 2;
            if (sz < 0) sz = 0; if (sz > 16) sz = 16;
            const bf16* src = (plane ? vbase_l : vbase_h) + (long long)d * NQd + colm;
            uint32_t dst = smem_u32((plane ? Vl : Vh) + d * LDV + cc);
            cp16(dst, src, sz);
        }
    };

    load_kv(0, 0);
    asm volatile("cp.async.commit_group;\n");

    uint32_t qfh[2][4], qfl[2][4];
    float o[4][4];
    float m0 = -1e30f, m1 = -1e30f, l0 = 0.f, l1 = 0.f;
#pragma unroll
    for (int jn = 0; jn < 4; jn++)
#pragma unroll
        for (int c = 0; c < 4; c++) o[jn][c] = 0.f;

    const float alpha = 0.17677669529663687f;
    constexpr int NKV = 16;

    for (int kb = 0; kb < NKV; kb++) {
        if (kb + 1 < NKV) {
            load_kv((kb + 1) & 1, (kb + 1) * LKV);
            asm volatile("cp.async.commit_group;\n");
            asm volatile("cp.async.wait_group 1;\n");
        } else {
            asm volatile("cp.async.wait_group 0;\n");
        }
        __syncthreads();

        if (kb == 0) {
            int row = w * 16 + lr;
#pragma unroll
            for (int t = 0; t < 2; t++) {
                int ks = t * 16;
                qfh[t][0] = *(const uint32_t*)(Qh + (row    ) * LDQ + ks + lc);
                qfh[t][1] = *(const uint32_t*)(Qh + (row + 8) * LDQ + ks + lc);
                qfh[t][2] = *(const uint32_t*)(Qh + (row    ) * LDQ + ks + lc + 8);
                qfh[t][3] = *(const uint32_t*)(Qh + (row + 8) * LDQ + ks + lc + 8);
                qfl[t][0] = *(const uint32_t*)(Ql + (row    ) * LDQ + ks + lc);
                qfl[t][1] = *(const uint32_t*)(Ql + (row + 8) * LDQ + ks + lc);
                qfl[t][2] = *(const uint32_t*)(Ql + (row    ) * LDQ + ks + lc + 8);
                qfl[t][3] = *(const uint32_t*)(Ql + (row + 8) * LDQ + ks + lc + 8);
            }
        }

        int st = kb & 1;
        int kv0 = kb * LKV;
        bf16* Kh = STG + st * KVSTAGE;
        bf16* Kl = Kh + KPA;
        bf16* Vh = Kl + KPA;
        bf16* Vl = Vh + VPA;

        float sa[8][4];
#pragma unroll
        for (int j = 0; j < 8; j++)
#pragma unroll
            for (int c = 0; c < 4; c++) sa[j][c] = 0.f;

#pragma unroll
        for (int t = 0; t < 2; t++) {
            int ks = t * 16;
            uint32_t bh[8][2], bl[8][2];
#pragma unroll
            for (int j = 0; j < 8; j++) {
                int kr = j * 8 + lr;
                bh[j][0] = *(const uint32_t*)(Kh + kr * LDQ + ks + lc);
                bh[j][1] = *(const uint32_t*)(Kh + kr * LDQ + ks + lc + 8);
                bl[j][0] = *(const uint32_t*)(Kl + kr * LDQ + ks + lc);
                bl[j][1] = *(const uint32_t*)(Kl + kr * LDQ + ks + lc + 8);
            }
#pragma unroll
            for (int j = 0; j < 8; j++) {
                mma16816(sa[j], qfh[t], bh[j]);
                mma16816(sa[j], qfh[t], bl[j]);
                mma16816(sa[j], qfl[t], bh[j]);
            }
        }

#pragma unroll
        for (int j = 0; j < 8; j++)
#pragma unroll
            for (int c = 0; c < 4; c++) sa[j][c] *= alpha;
        if (kv0 + LKV > NQd) {
#pragma unroll
            for (int j = 0; j < 8; j++) {
                int cb = kv0 + 8 * j + lc;
                if (cb     >= NQd) { sa[j][0] = -1e30f; sa[j][2] = -1e30f; }
                if (cb + 1 >= NQd) { sa[j][1] = -1e30f; sa[j][3] = -1e30f; }
            }
        }

        float mx0 = -1e30f, mx1 = -1e30f;
#pragma unroll
        for (int j = 0; j < 8; j++) {
            mx0 = fmaxf(mx0, fmaxf(sa[j][0], sa[j][1]));
            mx1 = fmaxf(mx1, fmaxf(sa[j][2], sa[j][3]));
        }
        mx0 = fmaxf(mx0, __shfl_xor_sync(0xffffffffu, mx0, 1));
        mx0 = fmaxf(mx0, __shfl_xor_sync(0xffffffffu, mx0, 2));
        mx1 = fmaxf(mx1, __shfl_xor_sync(0xffffffffu, mx1, 1));
        mx1 = fmaxf(mx1, __shfl_xor_sync(0xffffffffu, mx1, 2));
        float mn0 = fmaxf(m0, mx0), mn1 = fmaxf(m1, mx1);
        float sc0 = __expf(m0 - mn0), sc1 = __expf(m1 - mn1);
        m0 = mn0; m1 = mn1;

        float su0 = 0.f, su1 = 0.f;
#pragma unroll
        for (int j = 0; j < 8; j++) {
            sa[j][0] = __expf(sa[j][0] - mn0);
            sa[j][1] = __expf(sa[j][1] - mn0);
            sa[j][2] = __expf(sa[j][2] - mn1);
            sa[j][3] = __expf(sa[j][3] - mn1);
            su0 += sa[j][0] + sa[j][1];
            su1 += sa[j][2] + sa[j][3];
        }
        su0 += __shfl_xor_sync(0xffffffffu, su0, 1);
        su0 += __shfl_xor_sync(0xffffffffu, su0, 2);
        su1 += __shfl_xor_sync(0xffffffffu, su1, 1);
        su1 += __shfl_xor_sync(0xffffffffu, su1, 2);
        l0 = l0 * sc0 + su0;
        l1 = l1 * sc1 + su1;

#pragma unroll
        for (int jn = 0; jn < 4; jn++) {
            o[jn][0] *= sc0; o[jn][1] *= sc0;
            o[jn][2] *= sc1; o[jn][3] *= sc1;
        }

#pragma unroll
        for (int t = 0; t < 4; t++) {
            int j0 = 2 * t, j1 = 2 * t + 1;
            uint32_t aph[4], apl[4];
            {
                float v00 = sa[j0][0], v01 = sa[j0][1], v02 = sa[j0][2], v03 = sa[j0][3];
                float v10 = sa[j1][0], v11 = sa[j1][1], v12 = sa[j1][2], v13 = sa[j1][3];
                bf16 h00 = __float2bfloat16(v00), h01 = __float2bfloat16(v01);
                bf16 h02 = __float2bfloat16(v02), h03 = __float2bfloat16(v03);
                bf16 h10 = __float2bfloat16(v10), h11 = __float2bfloat16(v11);
                bf16 h12 = __float2bfloat16(v12), h13 = __float2bfloat16(v13);
                aph[0] = ((uint32_t)*(uint16_t*)&h00) | ((uint32_t)*(uint16_t*)&h01 << 16);
                aph[1] = ((uint32_t)*(uint16_t*)&h02) | ((uint32_t)*(uint16_t*)&h03 << 16);
                aph[2] = ((uint32_t)*(uint16_t*)&h10) | ((uint32_t)*(uint16_t*)&h11 << 16);
                aph[3] = ((uint32_t)*(uint16_t*)&h12) | ((uint32_t)*(uint16_t*)&h13 << 16);
                apl[0] = pack_bf2(v00 - __bfloat162float(h00), v01 - __bfloat162float(h01));
                apl[1] = pack_bf2(v02 - __bfloat162float(h02), v03 - __bfloat162float(h03));
                apl[2] = pack_bf2(v10 - __bfloat162float(h10), v11 - __bfloat162float(h11));
                apl[3] = pack_bf2(v12 - __bfloat162float(h12), v13 - __bfloat162float(h13));
            }
            int ks = t * 16;
#pragma unroll
            for (int jn = 0; jn < 4; jn++) {
                int vr = jn * 8 + lr;
                uint32_t bvh[2], bvl[2];
                bvh[0] = *(const uint32_t*)(Vh + vr * LDV + ks + lc);
                bvh[1] = *(const uint32_t*)(Vh + vr * LDV + ks + lc + 8);
                bvl[0] = *(const uint32_t*)(Vl + vr * LDV + ks + lc);
                bvl[1] = *(const uint32_t*)(Vl + vr * LDV + ks + lc + 8);
                mma16816(o[jn], aph, bvh);
                mma16816(o[jn], aph, bvl);
                mma16816(o[jn], apl, bvh);
            }
        }
        __syncthreads();
    }

    float il0 = 1.f / l0, il1 = 1.f / l1;
    int qa = q0 + w * 16 + lr;
    int qb = qa + 8;
#pragma unroll
    for (int jn = 0; jn < 4; jn++) {
        int d = jn * 8 + lc;
        if (qa < NQd) {
            long long oa = ((long long)b * NQd + qa) * Cd + h * 32 + d;
            split_write(aoh, aol, oa,     o[jn][0] * il0);
            split_write(aoh, aol, oa + 1, o[jn][1] * il0);
        }
        if (qb < NQd) {
            long long ob = ((long long)b * NQd + qb) * Cd + h * 32 + d;
            split_write(aoh, aol, ob,     o[jn][2] * il1);
            split_write(aoh, aol, ob + 1, o[jn][3] * il1);
        }
    }
}

// ---------------- prep: transpose query / add pos + split ----------------
__global__ void prep0_kernel(const float* __restrict__ query,
                             const float* __restrict__ qpos,
                             float* __restrict__ xq,
                             bf16* __restrict__ xq_h, bf16* __restrict__ xq_l,
                             bf16* __restrict__ qk_h, bf16* __restrict__ qk_l)
{
    int r = blockIdx.x, t = threadIdx.x;
    int b = r / NQd, q = r - b * NQd;
    long long src = ((long long)q * BSd + b) * Cd + t;
    long long dst = (long long)r * Cd + t;
    float x = query[src];
    float qp = qpos[src];
    xq[dst] = x;
    split_write(xq_h, xq_l, dst, x);
    split_write(qk_h, qk_l, dst, x + qp);
}

// ---------------- merged weight splits ----------------
struct SplitJob { const float* s; bf16* h; bf16* l; int n; };
struct SplitJobs6 { SplitJob j[6]; };
__global__ void split_multi_kernel(SplitJobs6 jobs)
{
    SplitJob jb = jobs.j[blockIdx.y];
    for (int i = blockIdx.x * 256 + threadIdx.x; i < jb.n; i += gridDim.x * 256)
        split_write(jb.h, jb.l, i, jb.s[i]);
}

// ---------------- value (NV,BS,C) -> per-batch hi/lo planes --------------
__global__ void value_split_kernel(const float* __restrict__ value,
                                   bf16* __restrict__ h, bf16* __restrict__ l)
{
    long long i = (long long)blockIdx.x * 256 + threadIdx.x;
    if (i >= (long long)BSd * NVd * Cd) return;
    int c = (int)(i & 255);
    long long rest = i >> 8;
    int n = (int)(rest % NVd);
    int b = (int)(rest / NVd);
    float v = value[((long long)n * BSd + b) * Cd + c];
    split_write(h, l, i, v);
}

// ---------------- vh transpose: qkv v-section -> vT[b,h][d][q] ----------
__global__ void vtrans_kernel(const bf16* __restrict__ qh, const bf16* __restrict__ ql,
                              bf16* __restrict__ th, bf16* __restrict__ tl)
{
    __shared__ bf16 tile_h[32][33];
    __shared__ bf16 tile_l[32][33];
    int q0 = blockIdx.x * 32, h = blockIdx.y, b = blockIdx.z;
    int tx = threadIdx.x, ty = threadIdx.y;
    for (int i = ty; i < 32; i += 8) {
        int q = q0 + i;
        bf16 vh = __float2bfloat16(0.f), vl = __float2bfloat16(0.f);
        if (q < NQd) {
            long long o = ((long long)(b * NQd + q)) * 768 + 512 + h * 32 + tx;
            vh = qh[o]; vl = ql[o];
        }
        tile_h[i][tx] = vh; tile_l[i][tx] = vl;
    }
    __syncthreads();
    for (int i = ty; i < 32; i += 8) {
        int d = i, q = q0 + tx;
        if (q < NQd) {
            long long o = ((long long)(b * NHd + h)) * (HDd * NQd) + (long long)d * NQd + q;
            th[o] = tile_h[tx][d];
            tl[o] = tile_l[tx][d];
        }
    }
}

// ---------------- residual + LayerNorm (+ optional split planes) --------
__global__ void add_ln_kernel(const float* __restrict__ a,
                              const float* __restrict__ r2,
                              const float* __restrict__ g,
                              const float* __restrict__ be,
                              float* __restrict__ out,
                              bf16* __restrict__ oh, bf16* __restrict__ ol,
                              int transpose_out)
{
    int r = blockIdx.x, t = threadIdx.x;
    __shared__ float sh[9];
    float v = a[(long long)r * Cd + t] + r2[(long long)r * Cd + t];

    float s = v;
#pragma unroll
    for (int o = 16; o; o >>= 1) s += __shfl_xor_sync(0xffffffffu, s, o);
    if ((t & 31) == 0) sh[t >> 5] = s;
    __syncthreads();
    if (t == 0) {
        float x = 0.f;
        for (int i = 0; i < 8; i++) x += sh[i];
        sh[8] = x * (1.f / Cd);
    }
    __syncthreads();
    float mean = sh[8];
    float d = v - mean;
    float s2 = d * d;
#pragma unroll
    for (int o = 16; o; o >>= 1) s2 += __shfl_xor_sync(0xffffffffu, s2, o);
    if ((t & 31) == 0) sh[t >> 5] = s2;
    __syncthreads();
    if (t == 0) {
        float x = 0.f;
        for (int i = 0; i < 8; i++) x += sh[i];
        sh[8] = rsqrtf(x * (1.f / Cd) + EPSd);
    }
    __syncthreads();
    float y = d * sh[8] * g[t] + be[t];

    long long oi;
    if (transpose_out) {
        int b = r / NQd, q = r - b * NQd;
        oi = ((long long)q * BSd + b) * Cd + t;
    } else {
        oi = (long long)r * Cd + t;
    }
    if (out) out[oi] = y;
    if (oh) split_write(oh, ol, (long long)r * Cd + t, y);
}

// ---------------- fused deformable sampling (-> hi/lo planes) ----------
__global__ void deform_kernel(const float* __restrict__ x1,
                              const float* __restrict__ qpos,
                              const float* __restrict__ refp,
                              const float* __restrict__ so_w, const float* __restrict__ so_b,
                              const float* __restrict__ aw_w, const float* __restrict__ aw_b,
                              const float* __restrict__ v,
                              bf16* __restrict__ oh, bf16* __restrict__ ol)
{
    int r = blockIdx.x, t = threadIdx.x;
    int b = r / NQd, q = r - b * NQd;

    __shared__ float qrow[Cd];
    __shared__ float offb[64];
    __shared__ float awb[32];
    __shared__ float ximb[32];
    __shared__ float yimb[32];

    qrow[t] = x1[(long long)r * Cd + t] + qpos[((long long)q * BSd + b) * Cd + t];
    __syncthreads();

    if (t < 64) {
        float s = so_b[t];
        const float* wrow = so_w + t * Cd;
#pragma unroll 8
        for (int c = 0; c < Cd; c++) s = fmaf(qrow[c], wrow[c], s);
        offb[t] = s;
    } else if (t < 96) {
        int j = t - 64;
        float s = aw_b[j];
        const float* wrow = aw_w + j * Cd;
#pragma unroll 8
        for (int c = 0; c < Cd; c++) s = fmaf(qrow[c], wrow[c], s);
        awb[j] = s;
    }
    __syncthreads();

    if (t < NHd) {
        float a0 = awb[t * 4 + 0], a1 = awb[t * 4 + 1], a2 = awb[t * 4 + 2], a3 = awb[t * 4 + 3];
        float m = fmaxf(fmaxf(a0, a1), fmaxf(a2, a3));
        float e0 = expf(a0 - m), e1 = expf(a1 - m), e2 = expf(a2 - m), e3 = expf(a3 - m);
        float inv = 1.f / (e0 + e1 + e2 + e3);
        awb[t * 4 + 0] = e0 * inv;
        awb[t * 4 + 1] = e1 * inv;
        awb[t * 4 + 2] = e2 * inv;
        awb[t * 4 + 3] = e3 * inv;
    }
    if (t < 32) {
        float rx = refp[((long long)b * NQd + q) * 2 + 0];
        float ry = refp[((long long)b * NQd + q) * 2 + 1];
        float lx = rx + offb[t * 2 + 0] * (1.f / Wb);
        float ly = ry + offb[t * 2 + 1] * (1.f / Hb);
        ximb[t] = lx * Wb - 0.5f;
        yimb[t] = ly * Hb - 0.5f;
    }
    __syncthreads();

    int h = t >> 5;
    float accT = 0.f;
#pragma unroll
    for (int p = 0; p < 4; p++) {
        int hp = h * 4 + p;
        float xim = ximb[hp], yim = yimb[hp];
        float x0f = floorf(xim), y0f = floorf(yim);
        float lx = xim - x0f, ly = yim - y0f;
        int x0 = (int)x0f, y0 = (int)y0f;
        float s = awb[hp];
        float acc = 0.f;
#pragma unroll
        for (int dy = 0; dy < 2; dy++)
#pragma unroll
            for (int dx = 0; dx < 2; dx++) {
                int xi = x0 + dx, yi = y0 + dy;
                if (xi >= 0 && xi < Wb && yi >= 0 && yi < Hb) {
                    float w = (dx ? lx : 1.f - lx) * (dy ? ly : 1.f - ly);
                    acc = fmaf(w, v[((long long)b * NVd + yi * Wb + xi) * Cd + t], acc);
                }
            }
        accT = fmaf(s, acc, accT);
    }
    split_write(oh, ol, (long long)r * Cd + t, accT);
}

// ---------------- launcher ----------------
static inline int cdiv(int a, int b) { return (a + b - 1) / b; }

extern "C" void kernel_launch(void* const* d_in, const int* in_sizes, int n_in,
                              void* d_out, int out_size)
{
    (void)in_sizes; (void)n_in; (void)out_size;
    const float* query  = (const float*)d_in[0];
    const float* value  = (const float*)d_in[1];
    const float* qpos   = (const float*)d_in[2];
    const float* refp   = (const float*)d_in[3];
    const float* in_w   = (const float*)d_in[6];
    const float* in_b   = (const float*)d_in[7];
    const float* mha_ow = (const float*)d_in[8];
    const float* mha_ob = (const float*)d_in[9];
    const float* so_w   = (const float*)d_in[10];
    const float* so_b   = (const float*)d_in[11];
    const float* aw_w   = (const float*)d_in[12];
    const float* aw_b   = (const float*)d_in[13];
    const float* vp_w   = (const float*)d_in[14];
    const float* vp_b   = (const float*)d_in[15];
    const float* op_w   = (const float*)d_in[16];
    const float* op_b   = (const float*)d_in[17];
    const float* ffn_w1 = (const float*)d_in[18];
    const float* ffn_b1 = (const float*)d_in[19];
    const float* ffn_w2 = (const float*)d_in[20];
    const float* ffn_b2 = (const float*)d_in[21];
    const float* ln1_g  = (const float*)d_in[22];
    const float* ln1_b  = (const float*)d_in[23];
    const float* ln2_g  = (const float*)d_in[24];
    const float* ln2_b  = (const float*)d_in[25];
    const float* ln3_g  = (const float*)d_in[26];
    const float* ln3_b  = (const float*)d_in[27];
    float* out = (float*)d_out;

    float* base = nullptr;
    cudaGetSymbolAddress((void**)&base, g_scratch);
    float* p = base;
    auto takeF = [&](long long n) { float* r = p; p += n; return r; };
    auto takeB = [&](long long n) { bf16* r = (bf16*)p; p += (n + 1) / 2; return r; };

    float* xq     = takeF(1024000);
    bf16* xq_h    = takeB(1024000);
    bf16* xq_l    = takeB(1024000);
    bf16* qk_h    = takeB(1024000);
    bf16* qk_l    = takeB(1024000);
    bf16* w_in_h  = takeB(196608);
    bf16* w_in_l  = takeB(196608);
    bf16* ow_h    = takeB(65536);
    bf16* ow_l    = takeB(65536);
    bf16* vpw_h   = takeB(65536);
    bf16* vpw_l   = takeB(65536);
    bf16* opw_h   = takeB(65536);
    bf16* opw_l   = takeB(65536);
    bf16* f1_h    = takeB(131072);
    bf16* f1_l    = takeB(131072);
    bf16* f2_h    = takeB(131072);
    bf16* f2_l    = takeB(131072);
    bf16* qkv_h   = takeB(3072000);
    bf16* qkv_l   = takeB(3072000);
    bf16* vT_h    = takeB(1024000);
    bf16* vT_l    = takeB(1024000);
    bf16* ao_h    = takeB(1024000);
    bf16* ao_l    = takeB(1024000);
    float* mha    = takeF(1024000);
    float* x1     = takeF(1024000);
    bf16* valA_h  = takeB(20480000);
    bf16* valA_l  = takeB(20480000);
    float* v      = takeF(20480000);
    bf16* df_h    = takeB(1024000);
    bf16* df_l    = takeB(1024000);
    float* dproj  = takeF(1024000);
    float* x2     = takeF(1024000);
    bf16* x2_h    = takeB(1024000);
    bf16* x2_l    = takeB(1024000);
    bf16* fh_h    = takeB(2048000);
    bf16* fh_l    = takeB(2048000);
    float* ffny   = takeF(1024000);

    // 64x128 tile, 3 stages: stage = 2*(64+128)*40 bf16 = 30720 B, x3 = 92160 B
    const int SMG = 92160;
    cudaFuncSetAttribute(bf_gemm<64,128,32,32>, cudaFuncAttributeMaxDynamicSharedMemorySize, SMG);
    cudaFuncSetAttribute(flash_kernel, cudaFuncAttributeMaxDynamicSharedMemorySize, 61440);

    // 1. prep
    prep0_kernel<<<M4, 256>>>(query, qpos, xq, xq_h, xq_l, qk_h, qk_l);

    // 2. weight splits (one launch) + value split
    SplitJobs6 jobs;
    jobs.j[0] = { in_w,   w_in_h, w_in_l, 196608 };
    jobs.j[1] = { mha_ow, ow_h,   ow_l,   65536 };
    jobs.j[2] = { vp_w,   vpw_h,  vpw_l,  65536 };
    jobs.j[3] = { op_w,   opw_h,  opw_l,  65536 };
    jobs.j[4] = { ffn_w1, f1_h,   f1_l,   131072 };
    jobs.j[5] = { ffn_w2, f2_h,   f2_l,   131072 };
    split_multi_kernel<<<dim3(96, 6), 256>>>(jobs);
    value_split_kernel<<<cdiv(BSd*NVd*Cd,256),256>>>(value, valA_h, valA_l);

    // 3. QK projection -> qkv planes cols [0,512)
    bf_gemm<64,128,32,32><<<dim3(63,4,1),256,SMG>>>(
        M4, 512, Cd,
        qk_h, qk_l, Cd, 0, 0,
        w_in_h, w_in_l, Cd, 0, 0,
        nullptr, qkv_h, qkv_l, 768, 0, 0,
        in_b, 1.f, 0, 1);

    // 4. V projection -> qkv planes cols [512,768)
    bf_gemm<64,128,32,32><<<dim3(63,2,1),256,SMG>>>(
        M4, 256, Cd,
        xq_h, xq_l, Cd, 0, 0,
        w_in_h + 512*Cd, w_in_l + 512*Cd, Cd, 0, 0,
        nullptr, qkv_h + 512, qkv_l + 512, 768, 0, 0,
        in_b + 512, 1.f, 0, 1);

    // 5. vh transpose -> vT[b,h][d][q]
    vtrans_kernel<<<dim3(32, NHd, BSd), dim3(32,8)>>>(qkv_h, qkv_l, vT_h, vT_l);

    // 6. flash attention -> ao planes
    flash_kernel<<<dim3(8, 32), 256, 61440>>>(qkv_h, qkv_l, vT_h, vT_l, ao_h, ao_l);

    // 7. MHA output projection -> mha fp32
    bf_gemm<64,128,32,32><<<dim3(63,2,1),256,SMG>>>(
        M4, 256, Cd,
        ao_h, ao_l, Cd, 0, 0,
        ow_h, ow_l, Cd, 0, 0,
        mha, nullptr, nullptr, Cd, 0, 0,
        mha_ob, 1.f, 0, 1);

    // 8. x1 = LN(x + mha)
    add_ln_kernel<<<M4, 256>>>(xq, mha, ln1_g, ln1_b, x1, nullptr, nullptr, 0);

    // 9. value projection -> v fp32 (batched over b)
    bf_gemm<64,128,32,32><<<dim3(313,2,4),256,SMG>>>(
        NVd, 256, Cd,
        valA_h, valA_l, Cd, 5120000LL, 0,
        vpw_h, vpw_l, Cd, 0, 0,
        v, nullptr, nullptr, Cd, 5120000LL, 0,
        vp_b, 1.f, 0, 1);

    // 10. deformable sampling -> deform planes
    deform_kernel<<<M4, 256>>>(x1, qpos, refp, so_w, so_b, aw_w, aw_b, v, df_h, df_l);

    // 11. deform output projection -> dproj fp32
    bf_gemm<64,128,32,32><<<dim3(63,2,1),256,SMG>>>(
        M4, 256, Cd,
        df_h, df_l, Cd, 0, 0,
        opw_h, opw_l, Cd, 0, 0,
        dproj, nullptr, nullptr, Cd, 0, 0,
        op_b, 1.f, 0, 1);

    // 12. x2 = LN(x1 + dproj) (+ planes for FFN)
    add_ln_kernel<<<M4, 256>>>(x1, dproj, ln2_g, ln2_b, x2, x2_h, x2_l, 0);

    // 13. FFN1 (+ReLU) -> ffnh planes
    bf_gemm<64,128,32,32><<<dim3(63,4,1),256,SMG>>>(
        M4, FFNd, Cd,
        x2_h, x2_l, Cd, 0, 0,
        f1_h, f1_l, Cd, 0, 0,
        nullptr, fh_h, fh_l, FFNd, 0, 0,
        ffn_b1, 1.f, 1, 1);

    // 14. FFN2 -> ffny fp32
    bf_gemm<64,128,32,32><<<dim3(63,2,1),256,SMG>>>(
        M4, 256, FFNd,
        fh_h, fh_l, FFNd, 0, 0,
        f2_h, f2_l, FFNd, 0, 0,
        ffny, nullptr, nullptr, Cd, 0, 0,
        ffn_b2, 1.f, 0, 1);

    // 15. x3 = LN(x2 + ffn) -> out (transposed)
    add_ln_kernel<<<M4, 256>>>(x2, ffny, ln3_g, ln3_b, out, nullptr, nullptr, 1);
}

// round 11
// speedup vs baseline: 1.0193x; 1.0193x over previous
#include <cuda_runtime.h>
#include <cuda_bf16.h>
#include <math.h>
#include <stdint.h>

typedef __nv_bfloat16 bf16;

// ---------------- problem constants ----------------
#define NQd 1000
#define BSd 4
#define Cd 256
#define NHd 8
#define HDd 32
#define NVd 20000
#define Wb 100
#define Hb 200
#define FFNd 512
#define M4 4000            // BS*NQ
#define EPSd 1e-5f

// ---------------- scratch (single device symbol, partitioned on host) ----
__device__ __align__(256) float g_scratch[70000000];

// ================= helpers =========================
__device__ __forceinline__ uint32_t smem_u32(const void* p) {
    return (uint32_t)__cvta_generic_to_shared(p);
}
__device__ __forceinline__ void cp16(uint32_t s, const void* g, int sz) {
    asm volatile("cp.async.cg.shared.global [%0], [%1], 16, %2;\n"
                 :: "r"(s), "l"(g), "r"(sz));
}
__device__ __forceinline__ void mma16816(float* d, const uint32_t* a, const uint32_t* b) {
    asm volatile(
        "mma.sync.aligned.m16n8k16.row.col.f32.bf16.bf16.f32 "
        "{%0,%1,%2,%3}, {%4,%5,%6,%7}, {%8,%9}, {%0,%1,%2,%3};\n"
        : "+f"(d[0]), "+f"(d[1]), "+f"(d[2]), "+f"(d[3])
        : "r"(a[0]), "r"(a[1]), "r"(a[2]), "r"(a[3]), "r"(b[0]), "r"(b[1]));
}
// ldmatrix x4: quads = {rows0-7 k0-7, rows8-15 k0-7, rows0-7 k8-15, rows8-15 k8-15}
// addr per lane: base + (lane%16)*row_stride + (lane/16)*16 bytes (folded by caller)
__device__ __forceinline__ void ldsm_x4(uint32_t& r0, uint32_t& r1, uint32_t& r2, uint32_t& r3,
                                        uint32_t addr) {
    asm volatile("ldmatrix.sync.aligned.m8n8.x4.shared.b16 {%0,%1,%2,%3}, [%4];"
                 : "=r"(r0), "=r"(r1), "=r"(r2), "=r"(r3) : "r"(addr));
}
__device__ __forceinline__ void split_write(bf16* H, bf16* L, long long off, float x) {
    bf16 h = __float2bfloat16(x);
    H[off] = h;
    L[off] = __float2bfloat16(x - __bfloat162float(h));
}
__device__ __forceinline__ uint32_t pack_bf2(float a, float b) {
    __nv_bfloat162 t = __floats2bfloat162_rn(a, b);
    return *(uint32_t*)&t;
}

// ================= pipelined bf16x3 tensor-core GEMM =====================
// 3-stage cp.async ring, one __syncthreads per k-block, ldmatrix frag loads.
template<int BM, int BN, int WM, int WN>
__global__ void __launch_bounds__((BM/WM)*(BN/WN)*32) bf_gemm(
    int M, int N, int K,
    const bf16* __restrict__ Ah, const bf16* __restrict__ Al, int sA,
    long long strA1, long long strA2,
    const bf16* __restrict__ Bh, const bf16* __restrict__ Bl, int sB,
    long long strB1, long long strB2,
    float* Cf, bf16* Ch, bf16* Cl, int ldc, long long strC1, long long strC2,
    const float* __restrict__ bias, float alpha, int relu, int batch2)
{
    constexpr int BK = 32;
    constexpr int NST = 3;
    constexpr int WARPS_M = BM / WM;
    constexpr int WARPS_N = BN / WN;
    constexpr int NT = WARPS_M * WARPS_N * 32;
    constexpr int LDA = 40;
    constexpr int MT = WM / 16;
    constexpr int NTn = WN / 8;
    constexpr int PA = BM * LDA;
    constexpr int PB = BN * LDA;
    constexpr int STAGE = 2 * PA + 2 * PB;
    constexpr int CA = BM * 4;
    constexpr int CT = (BM + BN) * 4;

    extern __shared__ __align__(16) bf16 sm[];

    int z = blockIdx.z;
    int i1 = z / batch2, i2 = z - i1 * batch2;
    Ah += i1 * strA1 + i2 * strA2;  Al += i1 * strA1 + i2 * strA2;
    Bh += i1 * strB1 + i2 * strB2;  Bl += i1 * strB1 + i2 * strB2;
    long long coff = i1 * strC1 + i2 * strC2;

    int m0 = blockIdx.x * BM;
    int n0 = blockIdx.y * BN;
    int tid = threadIdx.x, lane = tid & 31, warp = tid >> 5;
    int wm = warp / WARPS_N, wn = warp - wm * WARPS_N;
    int lr = lane >> 2, lc = (lane & 3) << 1;

    // ldmatrix per-lane offsets (bytes): row = lane%16, k-half = lane/16
    uint32_t aoffB = (uint32_t)(((wm * WM + (lane & 15)) * LDA + ((lane >> 4) << 3)) * 2);
    uint32_t boffB = (uint32_t)(((wn * WN + (lane & 15)) * LDA + ((lane >> 4) << 3)) * 2);

    float acc[MT][NTn][4];
#pragma unroll
    for (int i = 0; i < MT; i++)
#pragma unroll
        for (int j = 0; j < NTn; j++)
#pragma unroll
            for (int c = 0; c < 4; c++) acc[i][j][c] = 0.f;

    int nkb = (K + BK - 1) / BK;

    auto load_stage = [&](int st, int k0) {
        bf16* basep = sm + st * STAGE;
        for (int c = tid; c < CT; c += NT) {
            if (c < CA) {
                int row = c >> 2, kc = (c & 3) << 3;
                int m = m0 + row, k = k0 + kc;
                int sz = 0;
                int mc = (m < M) ? m : (M - 1);
                int kcl = (k < K) ? k : 0;
                if (m < M && k < K) { sz = (K - k) * 2; if (sz > 16) sz = 16; }
                long long go = (long long)mc * sA + kcl;
                uint32_t s0 = smem_u32(basep + row * LDA + kc);
                cp16(s0, Ah + go, sz);
                cp16(s0 + PA * 2, Al + go, sz);
            } else {
                int cc = c - CA;
                int row = cc >> 2, kc = (cc & 3) << 3;
                int n = n0 + row, k = k0 + kc;
                int sz = 0;
                int nc = (n < N) ? n : (N - 1);
                int kcl = (k < K) ? k : 0;
                if (n < N && k < K) { sz = (K - k) * 2; if (sz > 16) sz = 16; }
                long long go = (long long)nc * sB + kcl;
                uint32_t s0 = smem_u32(basep + 2 * PA + row * LDA + kc);
                cp16(s0, Bh + go, sz);
                cp16(s0 + PB * 2, Bl + go, sz);
            }
        }
    };

    auto compute = [&](int st) {
        uint32_t base = smem_u32(sm + st * STAGE);
        uint32_t aAh = base + aoffB;
        uint32_t aAl = aAh + PA * 2;
        uint32_t aBh = base + 2 * PA * 2 + boffB;
        uint32_t aBl = aBh + PB * 2;
#pragma unroll
        for (int ks = 0; ks < BK; ks += 16) {
            uint32_t af[MT][4], bhf[NTn][2], blf[NTn][2];
#pragma unroll
            for (int i = 0; i < MT; i++)
                ldsm_x4(af[i][0], af[i][1], af[i][2], af[i][3],
                        aAh + (uint32_t)((i * 16 * LDA + ks) * 2));
#pragma unroll
            for (int pr = 0; pr < NTn / 2; pr++) {
                uint32_t t0, t1, t2, t3;
                ldsm_x4(t0, t1, t2, t3, aBh + (uint32_t)((pr * 16 * LDA + ks) * 2));
                bhf[2*pr][0] = t0; bhf[2*pr+1][0] = t1;
                bhf[2*pr][1] = t2; bhf[2*pr+1][1] = t3;
                ldsm_x4(t0, t1, t2, t3, aBl + (uint32_t)((pr * 16 * LDA + ks) * 2));
                blf[2*pr][0] = t0; blf[2*pr+1][0] = t1;
                blf[2*pr][1] = t2; blf[2*pr+1][1] = t3;
            }
#pragma unroll
            for (int i = 0; i < MT; i++)
#pragma unroll
                for (int j = 0; j < NTn; j++) {
                    mma16816(acc[i][j], af[i], bhf[j]);   // hi*hi
                    mma16816(acc[i][j], af[i], blf[j]);   // hi*lo
                }
#pragma unroll
            for (int i = 0; i < MT; i++)
                ldsm_x4(af[i][0], af[i][1], af[i][2], af[i][3],
                        aAl + (uint32_t)((i * 16 * LDA + ks) * 2));
#pragma unroll
            for (int i = 0; i < MT; i++)
#pragma unroll
                for (int j = 0; j < NTn; j++)
                    mma16816(acc[i][j], af[i], bhf[j]);   // lo*hi
        }
    };

    load_stage(0, 0);
    asm volatile("cp.async.commit_group;\n");
    if (nkb > 1) {
        load_stage(1, BK);
        asm volatile("cp.async.commit_group;\n");
    }
    for (int kb = 0; kb < nkb; kb++) {
        if (kb + 1 < nkb) asm volatile("cp.async.wait_group 1;\n");
        else              asm volatile("cp.async.wait_group 0;\n");
        __syncthreads();
        compute(kb % NST);
        if (kb + 2 < nkb) {
            load_stage((kb + 2) % NST, (kb + 2) * BK);
            asm volatile("cp.async.commit_group;\n");
        }
    }

    float* Cfp = Cf ? Cf + coff : nullptr;
    bf16* Chp = Ch ? Ch + coff : nullptr;
    bf16* Clp = Cl ? Cl + coff : nullptr;
#pragma unroll
    for (int i = 0; i < MT; i++) {
        int row0 = m0 + wm * WM + i * 16 + lr;
#pragma unroll
        for (int j = 0; j < NTn; j++) {
            int col0 = n0 + wn * WN + j * 8 + lc;
#pragma unroll
            for (int c = 0; c < 4; c++) {
                int m = row0 + ((c >> 1) << 3);
                int n = col0 + (c & 1);
                if (m < M && n < N) {
                    float vv = acc[i][j][c] * alpha;
                    if (bias) vv += bias[n];
                    if (relu) vv = fmaxf(vv, 0.f);
                    long long o = (long long)m * ldc + n;
                    if (Cfp) Cfp[o] = vv;
                    if (Chp) {
                        bf16 hh = __float2bfloat16(vv);
                        Chp[o] = hh;
                        Clp[o] = __float2bfloat16(vv - __bfloat162float(hh));
                    }
                }
            }
        }
    }
}

// ================= flash attention (bf16x3, online softmax, ldmatrix) ====
__global__ void __launch_bounds__(256) flash_kernel(
    const bf16* __restrict__ qkvh, const bf16* __restrict__ qkvl,
    const bf16* __restrict__ vTh,  const bf16* __restrict__ vTl,
    bf16* __restrict__ aoh, bf16* __restrict__ aol)
{
    constexpr int LKV = 64;
    constexpr int LDQ = 40, LDV = 72;
    constexpr int QPA = 128 * LDQ;
    constexpr int KPA = LKV * LDQ;
    constexpr int VPA = 32 * LDV;
    constexpr int KVSTAGE = 2 * KPA + 2 * VPA;

    extern __shared__ __align__(16) bf16 smf[];
    bf16* Qh = smf;
    bf16* Ql = smf + QPA;
    bf16* STG = smf + 2 * QPA;

    int bz = blockIdx.y;
    int b = bz >> 3, h = bz & 7;
    int q0 = blockIdx.x * 128;
    int tid = threadIdx.x, lane = tid & 31, w = tid >> 5;
    int lr = lane >> 2, lc = (lane & 3) << 1;

    // ldmatrix per-lane byte offsets
    uint32_t qoffB = (uint32_t)(((w * 16 + (lane & 15)) * LDQ + ((lane >> 4) << 3)) * 2);
    uint32_t koffB = (uint32_t)(((lane & 15) * LDQ + ((lane >> 4) << 3)) * 2);
    uint32_t voffB = (uint32_t)(((lane & 15) * LDV + ((lane >> 4) << 3)) * 2);

    const bf16* qbase_h = qkvh + (long long)b * NQd * 768 + h * 32;
    const bf16* qbase_l = qkvl + (long long)b * NQd * 768 + h * 32;
    const bf16* vbase_h = vTh + (long long)bz * (HDd * NQd);
    const bf16* vbase_l = vTl + (long long)bz * (HDd * NQd);

    for (int c = tid; c < 1024; c += 256) {
        int plane = c >> 9, rem = c & 511;
        int row = rem >> 2, kc = (rem & 3) << 3;
        int q = q0 + row;
        int qm = (q < NQd) ? q : (NQd - 1);
        int sz = (q < NQd) ? 16 : 0;
        const bf16* src = (plane ? qbase_l : qbase_h) + (long long)qm * 768 + kc;
        uint32_t dst = smem_u32((plane ? Ql : Qh) + row * LDQ + kc);
        cp16(dst, src, sz);
    }

    auto load_kv = [&](int st, int kv0) {
        bf16* Kh = STG + st * KVSTAGE;
        bf16* Kl = Kh + KPA;
        bf16* Vh = Kl + KPA;
        bf16* Vl = Vh + VPA;
        for (int c = tid; c < 512; c += 256) {
            int plane = c >> 8, rem = c & 255;
            int row = rem >> 2, kc = (rem & 3) << 3;
            int kv = kv0 + row;
            int kvm = (kv < NQd) ? kv : (NQd - 1);
            int sz = (kv < NQd) ? 16 : 0;
            const bf16* src = (plane ? qbase_l : qbase_h) + (long long)kvm * 768 + 256 + kc;
            uint32_t dst = smem_u32((plane ? Kl : Kh) + row * LDQ + kc);
            cp16(dst, src, sz);
        }
        for (int c = tid; c < 512; c += 256) {
            int plane = c >> 8, rem = c & 255;
            int d = rem >> 3, cc = (rem & 7) << 3;
            int col = kv0 + cc;
            int colm = (col < NQd) ? col : (NQd - 8);
            int sz = (NQd - col) * 2;
            if (sz < 0) sz = 0; if (sz > 16) sz = 16;
            const bf16* src = (plane ? vbase_l : vbase_h) + (long long)d * NQd + colm;
            uint32_t dst = smem_u32((plane ? Vl : Vh) + d * LDV + cc);
            cp16(dst, src, sz);
        }
    };

    load_kv(0, 0);
    asm volatile("cp.async.commit_group;\n");

    uint32_t qfh[2][4], qfl[2][4];
    float o[4][4];
    float m0 = -1e30f, m1 = -1e30f, l0 = 0.f, l1 = 0.f;
#pragma unroll
    for (int jn = 0; jn < 4; jn++)
#pragma unroll
        for (int c = 0; c < 4; c++) o[jn][c] = 0.f;

    const float alpha = 0.17677669529663687f;
    constexpr int NKV = 16;

    for (int kb = 0; kb < NKV; kb++) {
        if (kb + 1 < NKV) {
            load_kv((kb + 1) & 1, (kb + 1) * LKV);
            asm volatile("cp.async.commit_group;\n");
            asm volatile("cp.async.wait_group 1;\n");
        } else {
            asm volatile("cp.async.wait_group 0;\n");
        }
        __syncthreads();

        if (kb == 0) {
            uint32_t qh0 = smem_u32(Qh) + qoffB;
            uint32_t ql0 = smem_u32(Ql) + qoffB;
#pragma unroll
            for (int t = 0; t < 2; t++) {
                ldsm_x4(qfh[t][0], qfh[t][1], qfh[t][2], qfh[t][3], qh0 + t * 32);
                ldsm_x4(qfl[t][0], qfl[t][1], qfl[t][2], qfl[t][3], ql0 + t * 32);
            }
        }

        int st = kb & 1;
        int kv0 = kb * LKV;
        bf16* Kh = STG + st * KVSTAGE;
        bf16* Kl = Kh + KPA;
        bf16* Vh = Kl + KPA;
        bf16* Vl = Vh + VPA;
        uint32_t kh0 = smem_u32(Kh) + koffB;
        uint32_t kl0 = smem_u32(Kl) + koffB;
        uint32_t vh0 = smem_u32(Vh) + voffB;
        uint32_t vl0 = smem_u32(Vl) + voffB;

        float sa[8][4];
#pragma unroll
        for (int j = 0; j < 8; j++)
#pragma unroll
            for (int c = 0; c < 4; c++) sa[j][c] = 0.f;

#pragma unroll
        for (int t = 0; t < 2; t++) {
            int ks = t * 16;
            uint32_t bh[8][2], bl[8][2];
#pragma unroll
            for (int pr = 0; pr < 4; pr++) {
                uint32_t t0, t1, t2, t3;
                ldsm_x4(t0, t1, t2, t3, kh0 + (uint32_t)((pr * 16 * LDQ + ks) * 2));
                bh[2*pr][0] = t0; bh[2*pr+1][0] = t1;
                bh[2*pr][1] = t2; bh[2*pr+1][1] = t3;
                ldsm_x4(t0, t1, t2, t3, kl0 + (uint32_t)((pr * 16 * LDQ + ks) * 2));
                bl[2*pr][0] = t0; bl[2*pr+1][0] = t1;
                bl[2*pr][1] = t2; bl[2*pr+1][1] = t3;
            }
#pragma unroll
            for (int j = 0; j < 8; j++) {
                mma16816(sa[j], qfh[t], bh[j]);
                mma16816(sa[j], qfh[t], bl[j]);
                mma16816(sa[j], qfl[t], bh[j]);
            }
        }

#pragma unroll
        for (int j = 0; j < 8; j++)
#pragma unroll
            for (int c = 0; c < 4; c++) sa[j][c] *= alpha;
        if (kv0 + LKV > NQd) {
#pragma unroll
            for (int j = 0; j < 8; j++) {
                int cb = kv0 + 8 * j + lc;
                if (cb     >= NQd) { sa[j][0] = -1e30f; sa[j][2] = -1e30f; }
                if (cb + 1 >= NQd) { sa[j][1] = -1e30f; sa[j][3] = -1e30f; }
            }
        }

        float mx0 = -1e30f, mx1 = -1e30f;
#pragma unroll
        for (int j = 0; j < 8; j++) {
            mx0 = fmaxf(mx0, fmaxf(sa[j][0], sa[j][1]));
            mx1 = fmaxf(mx1, fmaxf(sa[j][2], sa[j][3]));
        }
        mx0 = fmaxf(mx0, __shfl_xor_sync(0xffffffffu, mx0, 1));
        mx0 = fmaxf(mx0, __shfl_xor_sync(0xffffffffu, mx0, 2));
        mx1 = fmaxf(mx1, __shfl_xor_sync(0xffffffffu, mx1, 1));
        mx1 = fmaxf(mx1, __shfl_xor_sync(0xffffffffu, mx1, 2));
        float mn0 = fmaxf(m0, mx0), mn1 = fmaxf(m1, mx1);
        float sc0 = __expf(m0 - mn0), sc1 = __expf(m1 - mn1);
        m0 = mn0; m1 = mn1;

        float su0 = 0.f, su1 = 0.f;
#pragma unroll
        for (int j = 0; j < 8; j++) {
            sa[j][0] = __expf(sa[j][0] - mn0);
            sa[j][1] = __expf(sa[j][1] - mn0);
            sa[j][2] = __expf(sa[j][2] - mn1);
            sa[j][3] = __expf(sa[j][3] - mn1);
            su0 += sa[j][0] + sa[j][1];
            su1 += sa[j][2] + sa[j][3];
        }
        su0 += __shfl_xor_sync(0xffffffffu, su0, 1);
        su0 += __shfl_xor_sync(0xffffffffu, su0, 2);
        su1 += __shfl_xor_sync(0xffffffffu, su1, 1);
        su1 += __shfl_xor_sync(0xffffffffu, su1, 2);
        l0 = l0 * sc0 + su0;
        l1 = l1 * sc1 + su1;

#pragma unroll
        for (int jn = 0; jn < 4; jn++) {
            o[jn][0] *= sc0; o[jn][1] *= sc0;
            o[jn][2] *= sc1; o[jn][3] *= sc1;
        }

#pragma unroll
        for (int t = 0; t < 4; t++) {
            int j0 = 2 * t, j1 = 2 * t + 1;
            uint32_t aph[4], apl[4];
            {
                float v00 = sa[j0][0], v01 = sa[j0][1], v02 = sa[j0][2], v03 = sa[j0][3];
                float v10 = sa[j1][0], v11 = sa[j1][1], v12 = sa[j1][2], v13 = sa[j1][3];
                bf16 h00 = __float2bfloat16(v00), h01 = __float2bfloat16(v01);
                bf16 h02 = __float2bfloat16(v02), h03 = __float2bfloat16(v03);
                bf16 h10 = __float2bfloat16(v10), h11 = __float2bfloat16(v11);
                bf16 h12 = __float2bfloat16(v12), h13 = __float2bfloat16(v13);
                aph[0] = ((uint32_t)*(uint16_t*)&h00) | ((uint32_t)*(uint16_t*)&h01 << 16);
                aph[1] = ((uint32_t)*(uint16_t*)&h02) | ((uint32_t)*(uint16_t*)&h03 << 16);
                aph[2] = ((uint32_t)*(uint16_t*)&h10) | ((uint32_t)*(uint16_t*)&h11 << 16);
                aph[3] = ((uint32_t)*(uint16_t*)&h12) | ((uint32_t)*(uint16_t*)&h13 << 16);
                apl[0] = pack_bf2(v00 - __bfloat162float(h00), v01 - __bfloat162float(h01));
                apl[1] = pack_bf2(v02 - __bfloat162float(h02), v03 - __bfloat162float(h03));
                apl[2] = pack_bf2(v10 - __bfloat162float(h10), v11 - __bfloat162float(h11));
                apl[3] = pack_bf2(v12 - __bfloat162float(h12), v13 - __bfloat162float(h13));
            }
            int ks = t * 16;
            uint32_t bvh[4][2], bvl[4][2];
#pragma unroll
            for (int pr = 0; pr < 2; pr++) {
                uint32_t t0, t1, t2, t3;
                ldsm_x4(t0, t1, t2, t3, vh0 + (uint32_t)((pr * 16 * LDV + ks) * 2));
                bvh[2*pr][0] = t0; bvh[2*pr+1][0] = t1;
                bvh[2*pr][1] = t2; bvh[2*pr+1][1] = t3;
                ldsm_x4(t0, t1, t2, t3, vl0 + (uint32_t)((pr * 16 * LDV + ks) * 2));
                bvl[2*pr][0] = t0; bvl[2*pr+1][0] = t1;
                bvl[2*pr][1] = t2; bvl[2*pr+1][1] = t3;
            }
#pragma unroll
            for (int jn = 0; jn < 4; jn++) {
                mma16816(o[jn], aph, bvh[jn]);
                mma16816(o[jn], aph, bvl[jn]);
                mma16816(o[jn], apl, bvh[jn]);
            }
        }
        __syncthreads();
    }

    float il0 = 1.f / l0, il1 = 1.f / l1;
    int qa = q0 + w * 16 + lr;
    int qb = qa + 8;
#pragma unroll
    for (int jn = 0; jn < 4; jn++) {
        int d = jn * 8 + lc;
        if (qa < NQd) {
            long long oa = ((long long)b * NQd + qa) * Cd + h * 32 + d;
            split_write(aoh, aol, oa,     o[jn][0] * il0);
            split_write(aoh, aol, oa + 1, o[jn][1] * il0);
        }
        if (qb < NQd) {
            long long ob = ((long long)b * NQd + qb) * Cd + h * 32 + d;
            split_write(aoh, aol, ob,     o[jn][2] * il1);
            split_write(aoh, aol, ob + 1, o[jn][3] * il1);
        }
    }
}

// ---------------- prep: transpose query / add pos + split ----------------
__global__ void prep0_kernel(const float* __restrict__ query,
                             const float* __restrict__ qpos,
                             float* __restrict__ xq,
                             bf16* __restrict__ xq_h, bf16* __restrict__ xq_l,
                             bf16* __restrict__ qk_h, bf16* __restrict__ qk_l)
{
    int r = blockIdx.x, t = threadIdx.x;
    int b = r / NQd, q = r - b * NQd;
    long long src = ((long long)q * BSd + b) * Cd + t;
    long long dst = (long long)r * Cd + t;
    float x = query[src];
    float qp = qpos[src];
    xq[dst] = x;
    split_write(xq_h, xq_l, dst, x);
    split_write(qk_h, qk_l, dst, x + qp);
}

// ---------------- merged weight splits ----------------
struct SplitJob { const float* s; bf16* h; bf16* l; int n; };
struct SplitJobs6 { SplitJob j[6]; };
__global__ void split_multi_kernel(SplitJobs6 jobs)
{
    SplitJob jb = jobs.j[blockIdx.y];
    for (int i = blockIdx.x * 256 + threadIdx.x; i < jb.n; i += gridDim.x * 256)
        split_write(jb.h, jb.l, i, jb.s[i]);
}

// ---------------- value (NV,BS,C) -> per-batch hi/lo planes --------------
__global__ void value_split_kernel(const float* __restrict__ value,
                                   bf16* __restrict__ h, bf16* __restrict__ l)
{
    long long i = (long long)blockIdx.x * 256 + threadIdx.x;
    if (i >= (long long)BSd * NVd * Cd) return;
    int c = (int)(i & 255);
    long long rest = i >> 8;
    int n = (int)(rest % NVd);
    int b = (int)(rest / NVd);
    float v = value[((long long)n * BSd + b) * Cd + c];
    split_write(h, l, i, v);
}

// ---------------- vh transpose: qkv v-section -> vT[b,h][d][q] ----------
__global__ void vtrans_kernel(const bf16* __restrict__ qh, const bf16* __restrict__ ql,
                              bf16* __restrict__ th, bf16* __restrict__ tl)
{
    __shared__ bf16 tile_h[32][33];
    __shared__ bf16 tile_l[32][33];
    int q0 = blockIdx.x * 32, h = blockIdx.y, b = blockIdx.z;
    int tx = threadIdx.x, ty = threadIdx.y;
    for (int i = ty; i < 32; i += 8) {
        int q = q0 + i;
        bf16 vh = __float2bfloat16(0.f), vl = __float2bfloat16(0.f);
        if (q < NQd) {
            long long o = ((long long)(b * NQd + q)) * 768 + 512 + h * 32 + tx;
            vh = qh[o]; vl = ql[o];
        }
        tile_h[i][tx] = vh; tile_l[i][tx] = vl;
    }
    __syncthreads();
    for (int i = ty; i < 32; i += 8) {
        int d = i, q = q0 + tx;
        if (q < NQd) {
            long long o = ((long long)(b * NHd + h)) * (HDd * NQd) + (long long)d * NQd + q;
            th[o] = tile_h[tx][d];
            tl[o] = tile_l[tx][d];
        }
    }
}

// ---------------- residual + LayerNorm (+ optional split planes) --------
__global__ void add_ln_kernel(const float* __restrict__ a,
                              const float* __restrict__ r2,
                              const float* __restrict__ g,
                              const float* __restrict__ be,
                              float* __restrict__ out,
                              bf16* __restrict__ oh, bf16* __restrict__ ol,
                              int transpose_out)
{
    int r = blockIdx.x, t = threadIdx.x;
    __shared__ float sh[9];
    float v = a[(long long)r * Cd + t] + r2[(long long)r * Cd + t];

    float s = v;
#pragma unroll
    for (int o = 16; o; o >>= 1) s += __shfl_xor_sync(0xffffffffu, s, o);
    if ((t & 31) == 0) sh[t >> 5] = s;
    __syncthreads();
    if (t == 0) {
        float x = 0.f;
        for (int i = 0; i < 8; i++) x += sh[i];
        sh[8] = x * (1.f / Cd);
    }
    __syncthreads();
    float mean = sh[8];
    float d = v - mean;
    float s2 = d * d;
#pragma unroll
    for (int o = 16; o; o >>= 1) s2 += __shfl_xor_sync(0xffffffffu, s2, o);
    if ((t & 31) == 0) sh[t >> 5] = s2;
    __syncthreads();
    if (t == 0) {
        float x = 0.f;
        for (int i = 0; i < 8; i++) x += sh[i];
        sh[8] = rsqrtf(x * (1.f / Cd) + EPSd);
    }
    __syncthreads();
    float y = d * sh[8] * g[t] + be[t];

    long long oi;
    if (transpose_out) {
        int b = r / NQd, q = r - b * NQd;
        oi = ((long long)q * BSd + b) * Cd + t;
    } else {
        oi = (long long)r * Cd + t;
    }
    if (out) out[oi] = y;
    if (oh) split_write(oh, ol, (long long)r * Cd + t, y);
}

// ---------------- fused deformable sampling (-> hi/lo planes) ----------
__global__ void deform_kernel(const float* __restrict__ x1,
                              const float* __restrict__ qpos,
                              const float* __restrict__ refp,
                              const float* __restrict__ so_w, const float* __restrict__ so_b,
                              const float* __restrict__ aw_w, const float* __restrict__ aw_b,
                              const float* __restrict__ v,
                              bf16* __restrict__ oh, bf16* __restrict__ ol)
{
    int r = blockIdx.x, t = threadIdx.x;
    int b = r / NQd, q = r - b * NQd;

    __shared__ float qrow[Cd];
    __shared__ float offb[64];
    __shared__ float awb[32];
    __shared__ float ximb[32];
    __shared__ float yimb[32];

    qrow[t] = x1[(long long)r * Cd + t] + qpos[((long long)q * BSd + b) * Cd + t];
    __syncthreads();

    if (t < 64) {
        float s = so_b[t];
        const float* wrow = so_w + t * Cd;
#pragma unroll 8
        for (int c = 0; c < Cd; c++) s = fmaf(qrow[c], wrow[c], s);
        offb[t] = s;
    } else if (t < 96) {
        int j = t - 64;
        float s = aw_b[j];
        const float* wrow = aw_w + j * Cd;
#pragma unroll 8
        for (int c = 0; c < Cd; c++) s = fmaf(qrow[c], wrow[c], s);
        awb[j] = s;
    }
    __syncthreads();

    if (t < NHd) {
        float a0 = awb[t * 4 + 0], a1 = awb[t * 4 + 1], a2 = awb[t * 4 + 2], a3 = awb[t * 4 + 3];
        float m = fmaxf(fmaxf(a0, a1), fmaxf(a2, a3));
        float e0 = expf(a0 - m), e1 = expf(a1 - m), e2 = expf(a2 - m), e3 = expf(a3 - m);
        float inv = 1.f / (e0 + e1 + e2 + e3);
        awb[t * 4 + 0] = e0 * inv;
        awb[t * 4 + 1] = e1 * inv;
        awb[t * 4 + 2] = e2 * inv;
        awb[t * 4 + 3] = e3 * inv;
    }
    if (t < 32) {
        float rx = refp[((long long)b * NQd + q) * 2 + 0];
        float ry = refp[((long long)b * NQd + q) * 2 + 1];
        float lx = rx + offb[t * 2 + 0] * (1.f / Wb);
        float ly = ry + offb[t * 2 + 1] * (1.f / Hb);
        ximb[t] = lx * Wb - 0.5f;
        yimb[t] = ly * Hb - 0.5f;
    }
    __syncthreads();

    int h = t >> 5;
    float accT = 0.f;
#pragma unroll
    for (int p = 0; p < 4; p++) {
        int hp = h * 4 + p;
        float xim = ximb[hp], yim = yimb[hp];
        float x0f = floorf(xim), y0f = floorf(yim);
        float lx = xim - x0f, ly = yim - y0f;
        int x0 = (int)x0f, y0 = (int)y0f;
        float s = awb[hp];
        float acc = 0.f;
#pragma unroll
        for (int dy = 0; dy < 2; dy++)
#pragma unroll
            for (int dx = 0; dx < 2; dx++) {
                int xi = x0 + dx, yi = y0 + dy;
                if (xi >= 0 && xi < Wb && yi >= 0 && yi < Hb) {
                    float w = (dx ? lx : 1.f - lx) * (dy ? ly : 1.f - ly);
                    acc = fmaf(w, v[((long long)b * NVd + yi * Wb + xi) * Cd + t], acc);
                }
            }
        accT = fmaf(s, acc, accT);
    }
    split_write(oh, ol, (long long)r * Cd + t, accT);
}

// ---------------- launcher ----------------
static inline int cdiv(int a, int b) { return (a + b - 1) / b; }

extern "C" void kernel_launch(void* const* d_in, const int* in_sizes, int n_in,
                              void* d_out, int out_size)
{
    (void)in_sizes; (void)n_in; (void)out_size;
    const float* query  = (const float*)d_in[0];
    const float* value  = (const float*)d_in[1];
    const float* qpos   = (const float*)d_in[2];
    const float* refp   = (const float*)d_in[3];
    const float* in_w   = (const float*)d_in[6];
    const float* in_b   = (const float*)d_in[7];
    const float* mha_ow = (const float*)d_in[8];
    const float* mha_ob = (const float*)d_in[9];
    const float* so_w   = (const float*)d_in[10];
    const float* so_b   = (const float*)d_in[11];
    const float* aw_w   = (const float*)d_in[12];
    const float* aw_b   = (const float*)d_in[13];
    const float* vp_w   = (const float*)d_in[14];
    const float* vp_b   = (const float*)d_in[15];
    const float* op_w   = (const float*)d_in[16];
    const float* op_b   = (const float*)d_in[17];
    const float* ffn_w1 = (const float*)d_in[18];
    const float* ffn_b1 = (const float*)d_in[19];
    const float* ffn_w2 = (const float*)d_in[20];
    const float* ffn_b2 = (const float*)d_in[21];
    const float* ln1_g  = (const float*)d_in[22];
    const float* ln1_b  = (const float*)d_in[23];
    const float* ln2_g  = (const float*)d_in[24];
    const float* ln2_b  = (const float*)d_in[25];
    const float* ln3_g  = (const float*)d_in[26];
    const float* ln3_b  = (const float*)d_in[27];
    float* out = (float*)d_out;

    float* base = nullptr;
    cudaGetSymbolAddress((void**)&base, g_scratch);
    float* p = base;
    auto takeF = [&](long long n) { float* r = p; p += n; return r; };
    auto takeB = [&](long long n) { bf16* r = (bf16*)p; p += (n + 1) / 2; return r; };

    float* xq     = takeF(1024000);
    bf16* xq_h    = takeB(1024000);
    bf16* xq_l    = takeB(1024000);
    bf16* qk_h    = takeB(1024000);
    bf16* qk_l    = takeB(1024000);
    bf16* w_in_h  = takeB(196608);
    bf16* w_in_l  = takeB(196608);
    bf16* ow_h    = takeB(65536);
    bf16* ow_l    = takeB(65536);
    bf16* vpw_h   = takeB(65536);
    bf16* vpw_l   = takeB(65536);
    bf16* opw_h   = takeB(65536);
    bf16* opw_l   = takeB(65536);
    bf16* f1_h    = takeB(131072);
    bf16* f1_l    = takeB(131072);
    bf16* f2_h    = takeB(131072);
    bf16* f2_l    = takeB(131072);
    bf16* qkv_h   = takeB(3072000);
    bf16* qkv_l   = takeB(3072000);
    bf16* vT_h    = takeB(1024000);
    bf16* vT_l    = takeB(1024000);
    bf16* ao_h    = takeB(1024000);
    bf16* ao_l    = takeB(1024000);
    float* mha    = takeF(1024000);
    float* x1     = takeF(1024000);
    bf16* valA_h  = takeB(20480000);
    bf16* valA_l  = takeB(20480000);
    float* v      = takeF(20480000);
    bf16* df_h    = takeB(1024000);
    bf16* df_l    = takeB(1024000);
    float* dproj  = takeF(1024000);
    float* x2     = takeF(1024000);
    bf16* x2_h    = takeB(1024000);
    bf16* x2_l    = takeB(1024000);
    bf16* fh_h    = takeB(2048000);
    bf16* fh_l    = takeB(2048000);
    float* ffny   = takeF(1024000);

    // 64x128 tile, 3 stages: stage = 2*(64+128)*40 bf16 = 30720 B, x3 = 92160 B
    const int SMG = 92160;
    cudaFuncSetAttribute(bf_gemm<64,128,32,32>, cudaFuncAttributeMaxDynamicSharedMemorySize, SMG);
    cudaFuncSetAttribute(flash_kernel, cudaFuncAttributeMaxDynamicSharedMemorySize, 61440);

    // 1. prep
    prep0_kernel<<<M4, 256>>>(query, qpos, xq, xq_h, xq_l, qk_h, qk_l);

    // 2. weight splits (one launch) + value split
    SplitJobs6 jobs;
    jobs.j[0] = { in_w,   w_in_h, w_in_l, 196608 };
    jobs.j[1] = { mha_ow, ow_h,   ow_l,   65536 };
    jobs.j[2] = { vp_w,   vpw_h,  vpw_l,  65536 };
    jobs.j[3] = { op_w,   opw_h,  opw_l,  65536 };
    jobs.j[4] = { ffn_w1, f1_h,   f1_l,   131072 };
    jobs.j[5] = { ffn_w2, f2_h,   f2_l,   131072 };
    split_multi_kernel<<<dim3(96, 6), 256>>>(jobs);
    value_split_kernel<<<cdiv(BSd*NVd*Cd,256),256>>>(value, valA_h, valA_l);

    // 3. QK projection -> qkv planes cols [0,512)
    bf_gemm<64,128,32,32><<<dim3(63,4,1),256,SMG>>>(
        M4, 512, Cd,
        qk_h, qk_l, Cd, 0, 0,
        w_in_h, w_in_l, Cd, 0, 0,
        nullptr, qkv_h, qkv_l, 768, 0, 0,
        in_b, 1.f, 0, 1);

    // 4. V projection -> qkv planes cols [512,768)
    bf_gemm<64,128,32,32><<<dim3(63,2,1),256,SMG>>>(
        M4, 256, Cd,
        xq_h, xq_l, Cd, 0, 0,
        w_in_h + 512*Cd, w_in_l + 512*Cd, Cd, 0, 0,
        nullptr, qkv_h + 512, qkv_l + 512, 768, 0, 0,
        in_b + 512, 1.f, 0, 1);

    // 5. vh transpose -> vT[b,h][d][q]
    vtrans_kernel<<<dim3(32, NHd, BSd), dim3(32,8)>>>(qkv_h, qkv_l, vT_h, vT_l);

    // 6. flash attention -> ao planes
    flash_kernel<<<dim3(8, 32), 256, 61440>>>(qkv_h, qkv_l, vT_h, vT_l, ao_h, ao_l);

    // 7. MHA output projection -> mha fp32
    bf_gemm<64,128,32,32><<<dim3(63,2,1),256,SMG>>>(
        M4, 256, Cd,
        ao_h, ao_l, Cd, 0, 0,
        ow_h, ow_l, Cd, 0, 0,
        mha, nullptr, nullptr, Cd, 0, 0,
        mha_ob, 1.f, 0, 1);

    // 8. x1 = LN(x + mha)
    add_ln_kernel<<<M4, 256>>>(xq, mha, ln1_g, ln1_b, x1, nullptr, nullptr, 0);

    // 9. value projection -> v fp32 (batched over b)
    bf_gemm<64,128,32,32><<<dim3(313,2,4),256,SMG>>>(
        NVd, 256, Cd,
        valA_h, valA_l, Cd, 5120000LL, 0,
        vpw_h, vpw_l, Cd, 0, 0,
        v, nullptr, nullptr, Cd, 5120000LL, 0,
        vp_b, 1.f, 0, 1);

    // 10. deformable sampling -> deform planes
    deform_kernel<<<M4, 256>>>(x1, qpos, refp, so_w, so_b, aw_w, aw_b, v, df_h, df_l);

    // 11. deform output projection -> dproj fp32
    bf_gemm<64,128,32,32><<<dim3(63,2,1),256,SMG>>>(
        M4, 256, Cd,
        df_h, df_l, Cd, 0, 0,
        opw_h, opw_l, Cd, 0, 0,
        dproj, nullptr, nullptr, Cd, 0, 0,
        op_b, 1.f, 0, 1);

    // 12. x2 = LN(x1 + dproj) (+ planes for FFN)
    add_ln_kernel<<<M4, 256>>>(x1, dproj, ln2_g, ln2_b, x2, x2_h, x2_l, 0);

    // 13. FFN1 (+ReLU) -> ffnh planes
    bf_gemm<64,128,32,32><<<dim3(63,4,1),256,SMG>>>(
        M4, FFNd, Cd,
        x2_h, x2_l, Cd, 0, 0,
        f1_h, f1_l, Cd, 0, 0,
        nullptr, fh_h, fh_l, FFNd, 0, 0,
        ffn_b1, 1.f, 1, 1);

    // 14. FFN2 -> ffny fp32
    bf_gemm<64,128,32,32><<<dim3(63,2,1),256,SMG>>>(
        M4, 256, FFNd,
        fh_h, fh_l, FFNd, 0, 0,
        f2_h, f2_l, FFNd, 0, 0,
        ffny, nullptr, nullptr, Cd, 0, 0,
        ffn_b2, 1.f, 0, 1);

    // 15. x3 = LN(x2 + ffn) -> out (transposed)
    add_ln_kernel<<<M4, 256>>>(x2, ffny, ln3_g, ln3_b, out, nullptr, nullptr, 1);
}

// round 13
// speedup vs baseline: 1.2086x; 1.1858x over previous
#include <cuda_runtime.h>
#include <cuda_bf16.h>
#include <math.h>
#include <stdint.h>

typedef __nv_bfloat16 bf16;

// ---------------- problem constants ----------------
#define NQd 1000
#define BSd 4
#define Cd 256
#define NHd 8
#define HDd 32
#define NVd 20000
#define Wb 100
#define Hb 200
#define FFNd 512
#define M4 4000            // BS*NQ
#define EPSd 1e-5f

// ---------------- scratch (single device symbol, partitioned on host) ----
__device__ __align__(256) float g_scratch[40000000];

// ================= helpers =========================
__device__ __forceinline__ uint32_t smem_u32(const void* p) {
    return (uint32_t)__cvta_generic_to_shared(p);
}
__device__ __forceinline__ void cp16(uint32_t s, const void* g, int sz) {
    asm volatile("cp.async.cg.shared.global [%0], [%1], 16, %2;\n"
                 :: "r"(s), "l"(g), "r"(sz));
}
__device__ __forceinline__ void mma16816(float* d, const uint32_t* a, const uint32_t* b) {
    asm volatile(
        "mma.sync.aligned.m16n8k16.row.col.f32.bf16.bf16.f32 "
        "{%0,%1,%2,%3}, {%4,%5,%6,%7}, {%8,%9}, {%0,%1,%2,%3};\n"
        : "+f"(d[0]), "+f"(d[1]), "+f"(d[2]), "+f"(d[3])
        : "r"(a[0]), "r"(a[1]), "r"(a[2]), "r"(a[3]), "r"(b[0]), "r"(b[1]));
}
__device__ __forceinline__ void ldsm_x4(uint32_t& r0, uint32_t& r1, uint32_t& r2, uint32_t& r3,
                                        uint32_t addr) {
    asm volatile("ldmatrix.sync.aligned.m8n8.x4.shared.b16 {%0,%1,%2,%3}, [%4];"
                 : "=r"(r0), "=r"(r1), "=r"(r2), "=r"(r3) : "r"(addr));
}
__device__ __forceinline__ void split_write(bf16* H, bf16* L, long long off, float x) {
    bf16 h = __float2bfloat16(x);
    H[off] = h;
    L[off] = __float2bfloat16(x - __bfloat162float(h));
}
__device__ __forceinline__ uint32_t pack_bf2(float a, float b) {
    __nv_bfloat162 t = __floats2bfloat162_rn(a, b);
    return *(uint32_t*)&t;
}

// ================= pipelined bf16x3 tensor-core GEMM =====================
// 3-stage cp.async ring, one __syncthreads per k-block, ldmatrix frag loads.
template<int BM, int BN, int WM, int WN>
__global__ void __launch_bounds__((BM/WM)*(BN/WN)*32) bf_gemm(
    int M, int N, int K,
    const bf16* __restrict__ Ah, const bf16* __restrict__ Al, int sA,
    long long strA1, long long strA2,
    const bf16* __restrict__ Bh, const bf16* __restrict__ Bl, int sB,
    long long strB1, long long strB2,
    float* Cf, bf16* Ch, bf16* Cl, int ldc, long long strC1, long long strC2,
    const float* __restrict__ bias, int biasStr, float alpha, int relu, int batch2)
{
    constexpr int BK = 32;
    constexpr int NST = 3;
    constexpr int WARPS_M = BM / WM;
    constexpr int WARPS_N = BN / WN;
    constexpr int NT = WARPS_M * WARPS_N * 32;
    constexpr int LDA = 40;
    constexpr int MT = WM / 16;
    constexpr int NTn = WN / 8;
    constexpr int PA = BM * LDA;
    constexpr int PB = BN * LDA;
    constexpr int STAGE = 2 * PA + 2 * PB;
    constexpr int CA = BM * 4;
    constexpr int CT = (BM + BN) * 4;

    extern __shared__ __align__(16) bf16 sm[];

    int z = blockIdx.z;
    int i1 = z / batch2, i2 = z - i1 * batch2;
    Ah += i1 * strA1 + i2 * strA2;  Al += i1 * strA1 + i2 * strA2;
    Bh += i1 * strB1 + i2 * strB2;  Bl += i1 * strB1 + i2 * strB2;
    if (bias) bias += (long long)i2 * biasStr;
    long long coff = i1 * strC1 + i2 * strC2;

    int m0 = blockIdx.x * BM;
    int n0 = blockIdx.y * BN;
    int tid = threadIdx.x, lane = tid & 31, warp = tid >> 5;
    int wm = warp / WARPS_N, wn = warp - wm * WARPS_N;
    int lr = lane >> 2, lc = (lane & 3) << 1;

    uint32_t aoffB = (uint32_t)(((wm * WM + (lane & 15)) * LDA + ((lane >> 4) << 3)) * 2);
    uint32_t boffB = (uint32_t)(((wn * WN + (lane & 15)) * LDA + ((lane >> 4) << 3)) * 2);

    float acc[MT][NTn][4];
#pragma unroll
    for (int i = 0; i < MT; i++)
#pragma unroll
        for (int j = 0; j < NTn; j++)
#pragma unroll
            for (int c = 0; c < 4; c++) acc[i][j][c] = 0.f;

    int nkb = (K + BK - 1) / BK;

    auto load_stage = [&](int st, int k0) {
        bf16* basep = sm + st * STAGE;
        for (int c = tid; c < CT; c += NT) {
            if (c < CA) {
                int row = c >> 2, kc = (c & 3) << 3;
                int m = m0 + row, k = k0 + kc;
                int sz = 0;
                int mc = (m < M) ? m : (M - 1);
                int kcl = (k < K) ? k : 0;
                if (m < M && k < K) { sz = (K - k) * 2; if (sz > 16) sz = 16; }
                long long go = (long long)mc * sA + kcl;
                uint32_t s0 = smem_u32(basep + row * LDA + kc);
                cp16(s0, Ah + go, sz);
                cp16(s0 + PA * 2, Al + go, sz);
            } else {
                int cc = c - CA;
                int row = cc >> 2, kc = (cc & 3) << 3;
                int n = n0 + row, k = k0 + kc;
                int sz = 0;
                int nc = (n < N) ? n : (N - 1);
                int kcl = (k < K) ? k : 0;
                if (n < N && k < K) { sz = (K - k) * 2; if (sz > 16) sz = 16; }
                long long go = (long long)nc * sB + kcl;
                uint32_t s0 = smem_u32(basep + 2 * PA + row * LDA + kc);
                cp16(s0, Bh + go, sz);
                cp16(s0 + PB * 2, Bl + go, sz);
            }
        }
    };

    auto compute = [&](int st) {
        uint32_t base = smem_u32(sm + st * STAGE);
        uint32_t aAh = base + aoffB;
        uint32_t aAl = aAh + PA * 2;
        uint32_t aBh = base + 2 * PA * 2 + boffB;
        uint32_t aBl = aBh + PB * 2;
#pragma unroll
        for (int ks = 0; ks < BK; ks += 16) {
            uint32_t af[MT][4], bhf[NTn][2], blf[NTn][2];
#pragma unroll
            for (int i = 0; i < MT; i++)
                ldsm_x4(af[i][0], af[i][1], af[i][2], af[i][3],
                        aAh + (uint32_t)((i * 16 * LDA + ks) * 2));
#pragma unroll
            for (int pr = 0; pr < NTn / 2; pr++) {
                uint32_t t0, t1, t2, t3;
                ldsm_x4(t0, t1, t2, t3, aBh + (uint32_t)((pr * 16 * LDA + ks) * 2));
                bhf[2*pr][0] = t0; bhf[2*pr+1][0] = t1;
                bhf[2*pr][1] = t2; bhf[2*pr+1][1] = t3;
                ldsm_x4(t0, t1, t2, t3, aBl + (uint32_t)((pr * 16 * LDA + ks) * 2));
                blf[2*pr][0] = t0; blf[2*pr+1][0] = t1;
                blf[2*pr][1] = t2; blf[2*pr+1][1] = t3;
            }
#pragma unroll
            for (int i = 0; i < MT; i++)
#pragma unroll
                for (int j = 0; j < NTn; j++) {
                    mma16816(acc[i][j], af[i], bhf[j]);   // hi*hi
                    mma16816(acc[i][j], af[i], blf[j]);   // hi*lo
                }
#pragma unroll
            for (int i = 0; i < MT; i++)
                ldsm_x4(af[i][0], af[i][1], af[i][2], af[i][3],
                        aAl + (uint32_t)((i * 16 * LDA + ks) * 2));
#pragma unroll
            for (int i = 0; i < MT; i++)
#pragma unroll
                for (int j = 0; j < NTn; j++)
                    mma16816(acc[i][j], af[i], bhf[j]);   // lo*hi
        }
    };

    load_stage(0, 0);
    asm volatile("cp.async.commit_group;\n");
    if (nkb > 1) {
        load_stage(1, BK);
        asm volatile("cp.async.commit_group;\n");
    }
    for (int kb = 0; kb < nkb; kb++) {
        if (kb + 1 < nkb) asm volatile("cp.async.wait_group 1;\n");
        else              asm volatile("cp.async.wait_group 0;\n");
        __syncthreads();
        compute(kb % NST);
        if (kb + 2 < nkb) {
            load_stage((kb + 2) % NST, (kb + 2) * BK);
            asm volatile("cp.async.commit_group;\n");
        }
    }

    float* Cfp = Cf ? Cf + coff : nullptr;
    bf16* Chp = Ch ? Ch + coff : nullptr;
    bf16* Clp = Cl ? Cl + coff : nullptr;
#pragma unroll
    for (int i = 0; i < MT; i++) {
        int row0 = m0 + wm * WM + i * 16 + lr;
#pragma unroll
        for (int j = 0; j < NTn; j++) {
            int col0 = n0 + wn * WN + j * 8 + lc;
#pragma unroll
            for (int c = 0; c < 4; c++) {
                int m = row0 + ((c >> 1) << 3);
                int n = col0 + (c & 1);
                if (m < M && n < N) {
                    float vv = acc[i][j][c] * alpha;
                    if (bias) vv += bias[n];
                    if (relu) vv = fmaxf(vv, 0.f);
                    long long o = (long long)m * ldc + n;
                    if (Cfp) Cfp[o] = vv;
                    if (Chp) {
                        bf16 hh = __float2bfloat16(vv);
                        Chp[o] = hh;
                        Clp[o] = __float2bfloat16(vv - __bfloat162float(hh));
                    }
                }
            }
        }
    }
}

// ================= flash attention (bf16x3, online softmax, ldmatrix) ====
__global__ void __launch_bounds__(256) flash_kernel(
    const bf16* __restrict__ qkvh, const bf16* __restrict__ qkvl,
    const bf16* __restrict__ vTh,  const bf16* __restrict__ vTl,
    bf16* __restrict__ aoh, bf16* __restrict__ aol)
{
    constexpr int LKV = 64;
    constexpr int LDQ = 40, LDV = 72;
    constexpr int QPA = 128 * LDQ;
    constexpr int KPA = LKV * LDQ;
    constexpr int VPA = 32 * LDV;
    constexpr int KVSTAGE = 2 * KPA + 2 * VPA;

    extern __shared__ __align__(16) bf16 smf[];
    bf16* Qh = smf;
    bf16* Ql = smf + QPA;
    bf16* STG = smf + 2 * QPA;

    int bz = blockIdx.y;
    int b = bz >> 3, h = bz & 7;
    int q0 = blockIdx.x * 128;
    int tid = threadIdx.x, lane = tid & 31, w = tid >> 5;
    int lr = lane >> 2, lc = (lane & 3) << 1;

    uint32_t qoffB = (uint32_t)(((w * 16 + (lane & 15)) * LDQ + ((lane >> 4) << 3)) * 2);
    uint32_t koffB = (uint32_t)(((lane & 15) * LDQ + ((lane >> 4) << 3)) * 2);
    uint32_t voffB = (uint32_t)(((lane & 15) * LDV + ((lane >> 4) << 3)) * 2);

    const bf16* qbase_h = qkvh + (long long)b * NQd * 768 + h * 32;
    const bf16* qbase_l = qkvl + (long long)b * NQd * 768 + h * 32;
    const bf16* vbase_h = vTh + (long long)bz * (HDd * NQd);
    const bf16* vbase_l = vTl + (long long)bz * (HDd * NQd);

    for (int c = tid; c < 1024; c += 256) {
        int plane = c >> 9, rem = c & 511;
        int row = rem >> 2, kc = (rem & 3) << 3;
        int q = q0 + row;
        int qm = (q < NQd) ? q : (NQd - 1);
        int sz = (q < NQd) ? 16 : 0;
        const bf16* src = (plane ? qbase_l : qbase_h) + (long long)qm * 768 + kc;
        uint32_t dst = smem_u32((plane ? Ql : Qh) + row * LDQ + kc);
        cp16(dst, src, sz);
    }

    auto load_kv = [&](int st, int kv0) {
        bf16* Kh = STG + st * KVSTAGE;
        bf16* Kl = Kh + KPA;
        bf16* Vh = Kl + KPA;
        bf16* Vl = Vh + VPA;
        for (int c = tid; c < 512; c += 256) {
            int plane = c >> 8, rem = c & 255;
            int row = rem >> 2, kc = (rem & 3) << 3;
            int kv = kv0 + row;
            int kvm = (kv < NQd) ? kv : (NQd - 1);
            int sz = (kv < NQd) ? 16 : 0;
            const bf16* src = (plane ? qbase_l : qbase_h) + (long long)kvm * 768 + 256 + kc;
            uint32_t dst = smem_u32((plane ? Kl : Kh) + row * LDQ + kc);
            cp16(dst, src, sz);
        }
        for (int c = tid; c < 512; c += 256) {
            int plane = c >> 8, rem = c & 255;
            int d = rem >> 3, cc = (rem & 7) << 3;
            int col = kv0 + cc;
            int colm = (col < NQd) ? col : (NQd - 8);
            int sz = (NQd - col) * 2;
            if (sz < 0) sz = 0; if (sz > 16) sz = 16;
            const bf16* src = (plane ? vbase_l : vbase_h) + (long long)d * NQd + colm;
            uint32_t dst = smem_u32((plane ? Vl : Vh) + d * LDV + cc);
            cp16(dst, src, sz);
        }
    };

    load_kv(0, 0);
    asm volatile("cp.async.commit_group;\n");

    uint32_t qfh[2][4], qfl[2][4];
    float o[4][4];
    float m0 = -1e30f, m1 = -1e30f, l0 = 0.f, l1 = 0.f;
#pragma unroll
    for (int jn = 0; jn < 4; jn++)
#pragma unroll
        for (int c = 0; c < 4; c++) o[jn][c] = 0.f;

    const float alpha = 0.17677669529663687f;
    constexpr int NKV = 16;

    for (int kb = 0; kb < NKV; kb++) {
        if (kb + 1 < NKV) {
            load_kv((kb + 1) & 1, (kb + 1) * LKV);
            asm volatile("cp.async.commit_group;\n");
            asm volatile("cp.async.wait_group 1;\n");
        } else {
            asm volatile("cp.async.wait_group 0;\n");
        }
        __syncthreads();

        if (kb == 0) {
            uint32_t qh0 = smem_u32(Qh) + qoffB;
            uint32_t ql0 = smem_u32(Ql) + qoffB;
#pragma unroll
            for (int t = 0; t < 2; t++) {
                ldsm_x4(qfh[t][0], qfh[t][1], qfh[t][2], qfh[t][3], qh0 + t * 32);
                ldsm_x4(qfl[t][0], qfl[t][1], qfl[t][2], qfl[t][3], ql0 + t * 32);
            }
        }

        int st = kb & 1;
        int kv0 = kb * LKV;
        bf16* Kh = STG + st * KVSTAGE;
        bf16* Kl = Kh + KPA;
        bf16* Vh = Kl + KPA;
        bf16* Vl = Vh + VPA;
        uint32_t kh0 = smem_u32(Kh) + koffB;
        uint32_t kl0 = smem_u32(Kl) + koffB;
        uint32_t vh0 = smem_u32(Vh) + voffB;
        uint32_t vl0 = smem_u32(Vl) + voffB;

        float sa[8][4];
#pragma unroll
        for (int j = 0; j < 8; j++)
#pragma unroll
            for (int c = 0; c < 4; c++) sa[j][c] = 0.f;

#pragma unroll
        for (int t = 0; t < 2; t++) {
            int ks = t * 16;
            uint32_t bh[8][2], bl[8][2];
#pragma unroll
            for (int pr = 0; pr < 4; pr++) {
                uint32_t t0, t1, t2, t3;
                ldsm_x4(t0, t1, t2, t3, kh0 + (uint32_t)((pr * 16 * LDQ + ks) * 2));
                bh[2*pr][0] = t0; bh[2*pr+1][0] = t1;
                bh[2*pr][1] = t2; bh[2*pr+1][1] = t3;
                ldsm_x4(t0, t1, t2, t3, kl0 + (uint32_t)((pr * 16 * LDQ + ks) * 2));
                bl[2*pr][0] = t0; bl[2*pr+1][0] = t1;
                bl[2*pr][1] = t2; bl[2*pr+1][1] = t3;
            }
#pragma unroll
            for (int j = 0; j < 8; j++) {
                mma16816(sa[j], qfh[t], bh[j]);
                mma16816(sa[j], qfh[t], bl[j]);
                mma16816(sa[j], qfl[t], bh[j]);
            }
        }

#pragma unroll
        for (int j = 0; j < 8; j++)
#pragma unroll
            for (int c = 0; c < 4; c++) sa[j][c] *= alpha;
        if (kv0 + LKV > NQd) {
#pragma unroll
            for (int j = 0; j < 8; j++) {
                int cb = kv0 + 8 * j + lc;
                if (cb     >= NQd) { sa[j][0] = -1e30f; sa[j][2] = -1e30f; }
                if (cb + 1 >= NQd) { sa[j][1] = -1e30f; sa[j][3] = -1e30f; }
            }
        }

        float mx0 = -1e30f, mx1 = -1e30f;
#pragma unroll
        for (int j = 0; j < 8; j++) {
            mx0 = fmaxf(mx0, fmaxf(sa[j][0], sa[j][1]));
            mx1 = fmaxf(mx1, fmaxf(sa[j][2], sa[j][3]));
        }
        mx0 = fmaxf(mx0, __shfl_xor_sync(0xffffffffu, mx0, 1));
        mx0 = fmaxf(mx0, __shfl_xor_sync(0xffffffffu, mx0, 2));
        mx1 = fmaxf(mx1, __shfl_xor_sync(0xffffffffu, mx1, 1));
        mx1 = fmaxf(mx1, __shfl_xor_sync(0xffffffffu, mx1, 2));
        float mn0 = fmaxf(m0, mx0), mn1 = fmaxf(m1, mx1);
        float sc0 = __expf(m0 - mn0), sc1 = __expf(m1 - mn1);
        m0 = mn0; m1 = mn1;

        float su0 = 0.f, su1 = 0.f;
#pragma unroll
        for (int j = 0; j < 8; j++) {
            sa[j][0] = __expf(sa[j][0] - mn0);
            sa[j][1] = __expf(sa[j][1] - mn0);
            sa[j][2] = __expf(sa[j][2] - mn1);
            sa[j][3] = __expf(sa[j][3] - mn1);
            su0 += sa[j][0] + sa[j][1];
            su1 += sa[j][2] + sa[j][3];
        }
        su0 += __shfl_xor_sync(0xffffffffu, su0, 1);
        su0 += __shfl_xor_sync(0xffffffffu, su0, 2);
        su1 += __shfl_xor_sync(0xffffffffu, su1, 1);
        su1 += __shfl_xor_sync(0xffffffffu, su1, 2);
        l0 = l0 * sc0 + su0;
        l1 = l1 * sc1 + su1;

#pragma unroll
        for (int jn = 0; jn < 4; jn++) {
            o[jn][0] *= sc0; o[jn][1] *= sc0;
            o[jn][2] *= sc1; o[jn][3] *= sc1;
        }

#pragma unroll
        for (int t = 0; t < 4; t++) {
            int j0 = 2 * t, j1 = 2 * t + 1;
            uint32_t aph[4], apl[4];
            {
                float v00 = sa[j0][0], v01 = sa[j0][1], v02 = sa[j0][2], v03 = sa[j0][3];
                float v10 = sa[j1][0], v11 = sa[j1][1], v12 = sa[j1][2], v13 = sa[j1][3];
                bf16 h00 = __float2bfloat16(v00), h01 = __float2bfloat16(v01);
                bf16 h02 = __float2bfloat16(v02), h03 = __float2bfloat16(v03);
                bf16 h10 = __float2bfloat16(v10), h11 = __float2bfloat16(v11);
                bf16 h12 = __float2bfloat16(v12), h13 = __float2bfloat16(v13);
                aph[0] = ((uint32_t)*(uint16_t*)&h00) | ((uint32_t)*(uint16_t*)&h01 << 16);
                aph[1] = ((uint32_t)*(uint16_t*)&h02) | ((uint32_t)*(uint16_t*)&h03 << 16);
                aph[2] = ((uint32_t)*(uint16_t*)&h10) | ((uint32_t)*(uint16_t*)&h11 << 16);
                aph[3] = ((uint32_t)*(uint16_t*)&h12) | ((uint32_t)*(uint16_t*)&h13 << 16);
                apl[0] = pack_bf2(v00 - __bfloat162float(h00), v01 - __bfloat162float(h01));
                apl[1] = pack_bf2(v02 - __bfloat162float(h02), v03 - __bfloat162float(h03));
                apl[2] = pack_bf2(v10 - __bfloat162float(h10), v11 - __bfloat162float(h11));
                apl[3] = pack_bf2(v12 - __bfloat162float(h12), v13 - __bfloat162float(h13));
            }
            int ks = t * 16;
            uint32_t bvh[4][2], bvl[4][2];
#pragma unroll
            for (int pr = 0; pr < 2; pr++) {
                uint32_t t0, t1, t2, t3;
                ldsm_x4(t0, t1, t2, t3, vh0 + (uint32_t)((pr * 16 * LDV + ks) * 2));
                bvh[2*pr][0] = t0; bvh[2*pr+1][0] = t1;
                bvh[2*pr][1] = t2; bvh[2*pr+1][1] = t3;
                ldsm_x4(t0, t1, t2, t3, vl0 + (uint32_t)((pr * 16 * LDV + ks) * 2));
                bvl[2*pr][0] = t0; bvl[2*pr+1][0] = t1;
                bvl[2*pr][1] = t2; bvl[2*pr+1][1] = t3;
            }
#pragma unroll
            for (int jn = 0; jn < 4; jn++) {
                mma16816(o[jn], aph, bvh[jn]);
                mma16816(o[jn], aph, bvl[jn]);
                mma16816(o[jn], apl, bvh[jn]);
            }
        }
        __syncthreads();
    }

    float il0 = 1.f / l0, il1 = 1.f / l1;
    int qa = q0 + w * 16 + lr;
    int qb = qa + 8;
#pragma unroll
    for (int jn = 0; jn < 4; jn++) {
        int d = jn * 8 + lc;
        if (qa < NQd) {
            long long oa = ((long long)b * NQd + qa) * Cd + h * 32 + d;
            split_write(aoh, aol, oa,     o[jn][0] * il0);
            split_write(aoh, aol, oa + 1, o[jn][1] * il0);
        }
        if (qb < NQd) {
            long long ob = ((long long)b * NQd + qb) * Cd + h * 32 + d;
            split_write(aoh, aol, ob,     o[jn][2] * il1);
            split_write(aoh, aol, ob + 1, o[jn][3] * il1);
        }
    }
}

// ---------------- prep: transpose query / add pos + split ----------------
__global__ void prep0_kernel(const float* __restrict__ query,
                             const float* __restrict__ qpos,
                             float* __restrict__ xq,
                             bf16* __restrict__ xq_h, bf16* __restrict__ xq_l,
                             bf16* __restrict__ qk_h, bf16* __restrict__ qk_l)
{
    int r = blockIdx.x, t = threadIdx.x;
    int b = r / NQd, q = r - b * NQd;
    long long src = ((long long)q * BSd + b) * Cd + t;
    long long dst = (long long)r * Cd + t;
    float x = query[src];
    float qp = qpos[src];
    xq[dst] = x;
    split_write(xq_h, xq_l, dst, x);
    split_write(qk_h, qk_l, dst, x + qp);
}

// ---------------- merged weight splits ----------------
struct SplitJob { const float* s; bf16* h; bf16* l; int n; };
struct SplitJobs6 { SplitJob j[6]; };
__global__ void split_multi_kernel(SplitJobs6 jobs)
{
    SplitJob jb = jobs.j[blockIdx.y];
    for (int i = blockIdx.x * 256 + threadIdx.x; i < jb.n; i += gridDim.x * 256)
        split_write(jb.h, jb.l, i, jb.s[i]);
}

// ---------------- vh transpose: qkv v-section -> vT[b,h][d][q] ----------
__global__ void vtrans_kernel(const bf16* __restrict__ qh, const bf16* __restrict__ ql,
                              bf16* __restrict__ th, bf16* __restrict__ tl)
{
    __shared__ bf16 tile_h[32][33];
    __shared__ bf16 tile_l[32][33];
    int q0 = blockIdx.x * 32, h = blockIdx.y, b = blockIdx.z;
    int tx = threadIdx.x, ty = threadIdx.y;
    for (int i = ty; i < 32; i += 8) {
        int q = q0 + i;
        bf16 vh = __float2bfloat16(0.f), vl = __float2bfloat16(0.f);
        if (q < NQd) {
            long long o = ((long long)(b * NQd + q)) * 768 + 512 + h * 32 + tx;
            vh = qh[o]; vl = ql[o];
        }
        tile_h[i][tx] = vh; tile_l[i][tx] = vl;
    }
    __syncthreads();
    for (int i = ty; i < 32; i += 8) {
        int d = i, q = q0 + tx;
        if (q < NQd) {
            long long o = ((long long)(b * NHd + h)) * (HDd * NQd) + (long long)d * NQd + q;
            th[o] = tile_h[tx][d];
            tl[o] = tile_l[tx][d];
        }
    }
}

// ---------------- residual + LayerNorm (+ optional split planes) --------
__global__ void add_ln_kernel(const float* __restrict__ a,
                              const float* __restrict__ r2,
                              const float* __restrict__ g,
                              const float* __restrict__ be,
                              float* __restrict__ out,
                              bf16* __restrict__ oh, bf16* __restrict__ ol,
                              int transpose_out)
{
    int r = blockIdx.x, t = threadIdx.x;
    __shared__ float sh[9];
    float v = a[(long long)r * Cd + t] + r2[(long long)r * Cd + t];

    float s = v;
#pragma unroll
    for (int o = 16; o; o >>= 1) s += __shfl_xor_sync(0xffffffffu, s, o);
    if ((t & 31) == 0) sh[t >> 5] = s;
    __syncthreads();
    if (t == 0) {
        float x = 0.f;
        for (int i = 0; i < 8; i++) x += sh[i];
        sh[8] = x * (1.f / Cd);
    }
    __syncthreads();
    float mean = sh[8];
    float d = v - mean;
    float s2 = d * d;
#pragma unroll
    for (int o = 16; o; o >>= 1) s2 += __shfl_xor_sync(0xffffffffu, s2, o);
    if ((t & 31) == 0) sh[t >> 5] = s2;
    __syncthreads();
    if (t == 0) {
        float x = 0.f;
        for (int i = 0; i < 8; i++) x += sh[i];
        sh[8] = rsqrtf(x * (1.f / Cd) + EPSd);
    }
    __syncthreads();
    float y = d * sh[8] * g[t] + be[t];

    long long oi;
    if (transpose_out) {
        int b = r / NQd, q = r - b * NQd;
        oi = ((long long)q * BSd + b) * Cd + t;
    } else {
        oi = (long long)r * Cd + t;
    }
    if (out) out[oi] = y;
    if (oh) split_write(oh, ol, (long long)r * Cd + t, y);
}

// ---------------- fused deformable sampling on RAW value ----------------
// Projection commutes with the bilinear gather:
//   out[b,q,h,:] = (sum_{p,corner} w * value_raw[idx]) @ vp_w[hslice]^T
// This kernel computes S[b,q][h*256+c] = weighted raw sum (fp32 exact),
// written as hi/lo planes; a small batched GEMM applies vp_w afterwards.
__global__ void deform_kernel(const float* __restrict__ x1,
                              const float* __restrict__ qpos,
                              const float* __restrict__ refp,
                              const float* __restrict__ so_w, const float* __restrict__ so_b,
                              const float* __restrict__ aw_w, const float* __restrict__ aw_b,
                              const float* __restrict__ value,
                              bf16* __restrict__ Shp, bf16* __restrict__ Slp)
{
    int r = blockIdx.x, t = threadIdx.x;
    int b = r / NQd, q = r - b * NQd;

    __shared__ float qrow[Cd];
    __shared__ float offb[64];
    __shared__ float awb[32];
    __shared__ int x0s[32];
    __shared__ int y0s[32];
    __shared__ float lxs[32];
    __shared__ float lys[32];

    qrow[t] = x1[(long long)r * Cd + t] + qpos[((long long)q * BSd + b) * Cd + t];
    __syncthreads();

    if (t < 64) {
        float s = so_b[t];
        const float* wrow = so_w + t * Cd;
#pragma unroll 8
        for (int c = 0; c < Cd; c++) s = fmaf(qrow[c], wrow[c], s);
        offb[t] = s;
    } else if (t < 96) {
        int j = t - 64;
        float s = aw_b[j];
        const float* wrow = aw_w + j * Cd;
#pragma unroll 8
        for (int c = 0; c < Cd; c++) s = fmaf(qrow[c], wrow[c], s);
        awb[j] = s;
    }
    __syncthreads();

    if (t < NHd) {
        float a0 = awb[t * 4 + 0], a1 = awb[t * 4 + 1], a2 = awb[t * 4 + 2], a3 = awb[t * 4 + 3];
        float m = fmaxf(fmaxf(a0, a1), fmaxf(a2, a3));
        float e0 = expf(a0 - m), e1 = expf(a1 - m), e2 = expf(a2 - m), e3 = expf(a3 - m);
        float inv = 1.f / (e0 + e1 + e2 + e3);
        awb[t * 4 + 0] = e0 * inv;
        awb[t * 4 + 1] = e1 * inv;
        awb[t * 4 + 2] = e2 * inv;
        awb[t * 4 + 3] = e3 * inv;
    }
    if (t < 32) {
        float rx = refp[((long long)b * NQd + q) * 2 + 0];
        float ry = refp[((long long)b * NQd + q) * 2 + 1];
        float lx = rx + offb[t * 2 + 0] * (1.f / Wb);
        float ly = ry + offb[t * 2 + 1] * (1.f / Hb);
        float xim = lx * Wb - 0.5f;
        float yim = ly * Hb - 0.5f;
        float x0f = floorf(xim), y0f = floorf(yim);
        x0s[t] = (int)x0f;
        y0s[t] = (int)y0f;
        lxs[t] = xim - x0f;
        lys[t] = yim - y0f;
    }
    __syncthreads();

    // gather raw value rows (channel t), accumulate per-head weighted sums
    const float* vbase = value + (long long)b * Cd + t;   // + n*(BSd*Cd)
#pragma unroll
    for (int h = 0; h < NHd; h++) {
        float s = 0.f;
#pragma unroll
        for (int p = 0; p < 4; p++) {
            int hp = h * 4 + p;
            int x0 = x0s[hp], y0 = y0s[hp];
            float lx = lxs[hp], ly = lys[hp];
            float aw = awb[hp];
#pragma unroll
            for (int dy = 0; dy < 2; dy++)
#pragma unroll
                for (int dx = 0; dx < 2; dx++) {
                    int xi = x0 + dx, yi = y0 + dy;
                    if (xi >= 0 && xi < Wb && yi >= 0 && yi < Hb) {
                        float w = (dx ? lx : 1.f - lx) * (dy ? ly : 1.f - ly);
                        s = fmaf(aw * w, vbase[(long long)(yi * Wb + xi) * (BSd * Cd)], s);
                    }
                }
        }
        split_write(Shp, Slp, (long long)r * 2048 + h * 256 + t, s);
    }
}

// ---------------- launcher ----------------
static inline int cdiv(int a, int b) { return (a + b - 1) / b; }

extern "C" void kernel_launch(void* const* d_in, const int* in_sizes, int n_in,
                              void* d_out, int out_size)
{
    (void)in_sizes; (void)n_in; (void)out_size;
    const float* query  = (const float*)d_in[0];
    const float* value  = (const float*)d_in[1];
    const float* qpos   = (const float*)d_in[2];
    const float* refp   = (const float*)d_in[3];
    const float* in_w   = (const float*)d_in[6];
    const float* in_b   = (const float*)d_in[7];
    const float* mha_ow = (const float*)d_in[8];
    const float* mha_ob = (const float*)d_in[9];
    const float* so_w   = (const float*)d_in[10];
    const float* so_b   = (const float*)d_in[11];
    const float* aw_w   = (const float*)d_in[12];
    const float* aw_b   = (const float*)d_in[13];
    const float* vp_w   = (const float*)d_in[14];
    const float* vp_b   = (const float*)d_in[15];
    const float* op_w   = (const float*)d_in[16];
    const float* op_b   = (const float*)d_in[17];
    const float* ffn_w1 = (const float*)d_in[18];
    const float* ffn_b1 = (const float*)d_in[19];
    const float* ffn_w2 = (const float*)d_in[20];
    const float* ffn_b2 = (const float*)d_in[21];
    const float* ln1_g  = (const float*)d_in[22];
    const float* ln1_b  = (const float*)d_in[23];
    const float* ln2_g  = (const float*)d_in[24];
    const float* ln2_b  = (const float*)d_in[25];
    const float* ln3_g  = (const float*)d_in[26];
    const float* ln3_b  = (const float*)d_in[27];
    float* out = (float*)d_out;

    float* base = nullptr;
    cudaGetSymbolAddress((void**)&base, g_scratch);
    float* p = base;
    auto takeF = [&](long long n) { float* r = p; p += n; return r; };
    auto takeB = [&](long long n) { bf16* r = (bf16*)p; p += (n + 1) / 2; return r; };

    float* xq     = takeF(1024000);
    bf16* xq_h    = takeB(1024000);
    bf16* xq_l    = takeB(1024000);
    bf16* qk_h    = takeB(1024000);
    bf16* qk_l    = takeB(1024000);
    bf16* w_in_h  = takeB(196608);
    bf16* w_in_l  = takeB(196608);
    bf16* ow_h    = takeB(65536);
    bf16* ow_l    = takeB(65536);
    bf16* vpw_h   = takeB(65536);
    bf16* vpw_l   = takeB(65536);
    bf16* opw_h   = takeB(65536);
    bf16* opw_l   = takeB(65536);
    bf16* f1_h    = takeB(131072);
    bf16* f1_l    = takeB(131072);
    bf16* f2_h    = takeB(131072);
    bf16* f2_l    = takeB(131072);
    bf16* qkv_h   = takeB(3072000);
    bf16* qkv_l   = takeB(3072000);
    bf16* vT_h    = takeB(1024000);
    bf16* vT_l    = takeB(1024000);
    bf16* ao_h    = takeB(1024000);
    bf16* ao_l    = takeB(1024000);
    float* mha    = takeF(1024000);
    float* x1     = takeF(1024000);
    bf16* S_h     = takeB(8192000);   // [b,q][h*256+c]
    bf16* S_l     = takeB(8192000);
    bf16* df_h    = takeB(1024000);
    bf16* df_l    = takeB(1024000);
    float* dproj  = takeF(1024000);
    float* x2     = takeF(1024000);
    bf16* x2_h    = takeB(1024000);
    bf16* x2_l    = takeB(1024000);
    bf16* fh_h    = takeB(2048000);
    bf16* fh_l    = takeB(2048000);
    float* ffny   = takeF(1024000);

    // 64x128 tile, 3 stages: stage = 2*(64+128)*40 bf16 = 30720 B, x3 = 92160 B
    const int SMG = 92160;
    // 64x32 tile, 3 stages: stage = 2*(64+32)*40 bf16 = 15360 B, x3 = 46080 B
    const int SMG32 = 46080;
    cudaFuncSetAttribute(bf_gemm<64,128,32,32>, cudaFuncAttributeMaxDynamicSharedMemorySize, SMG);
    cudaFuncSetAttribute(bf_gemm<64,32,32,16>,  cudaFuncAttributeMaxDynamicSharedMemorySize, SMG32);
    cudaFuncSetAttribute(flash_kernel, cudaFuncAttributeMaxDynamicSharedMemorySize, 61440);

    // 1. prep
    prep0_kernel<<<M4, 256>>>(query, qpos, xq, xq_h, xq_l, qk_h, qk_l);

    // 2. weight splits (one launch)
    SplitJobs6 jobs;
    jobs.j[0] = { in_w,   w_in_h, w_in_l, 196608 };
    jobs.j[1] = { mha_ow, ow_h,   ow_l,   65536 };
    jobs.j[2] = { vp_w,   vpw_h,  vpw_l,  65536 };
    jobs.j[3] = { op_w,   opw_h,  opw_l,  65536 };
    jobs.j[4] = { ffn_w1, f1_h,   f1_l,   131072 };
    jobs.j[5] = { ffn_w2, f2_h,   f2_l,   131072 };
    split_multi_kernel<<<dim3(96, 6), 256>>>(jobs);

    // 3. QK projection -> qkv planes cols [0,512)
    bf_gemm<64,128,32,32><<<dim3(63,4,1),256,SMG>>>(
        M4, 512, Cd,
        qk_h, qk_l, Cd, 0, 0,
        w_in_h, w_in_l, Cd, 0, 0,
        nullptr, qkv_h, qkv_l, 768, 0, 0,
        in_b, 0, 1.f, 0, 1);

    // 4. V projection -> qkv planes cols [512,768)
    bf_gemm<64,128,32,32><<<dim3(63,2,1),256,SMG>>>(
        M4, 256, Cd,
        xq_h, xq_l, Cd, 0, 0,
        w_in_h + 512*Cd, w_in_l + 512*Cd, Cd, 0, 0,
        nullptr, qkv_h + 512, qkv_l + 512, 768, 0, 0,
        in_b + 512, 0, 1.f, 0, 1);

    // 5. vh transpose -> vT[b,h][d][q]
    vtrans_kernel<<<dim3(32, NHd, BSd), dim3(32,8)>>>(qkv_h, qkv_l, vT_h, vT_l);

    // 6. flash attention -> ao planes
    flash_kernel<<<dim3(8, 32), 256, 61440>>>(qkv_h, qkv_l, vT_h, vT_l, ao_h, ao_l);

    // 7. MHA output projection -> mha fp32
    bf_gemm<64,128,32,32><<<dim3(63,2,1),256,SMG>>>(
        M4, 256, Cd,
        ao_h, ao_l, Cd, 0, 0,
        ow_h, ow_l, Cd, 0, 0,
        mha, nullptr, nullptr, Cd, 0, 0,
        mha_ob, 0, 1.f, 0, 1);

    // 8. x1 = LN(x + mha)
    add_ln_kernel<<<M4, 256>>>(xq, mha, ln1_g, ln1_b, x1, nullptr, nullptr, 0);

    // 9. deformable sampling on RAW value -> S planes [b,q][h*256+c]
    deform_kernel<<<M4, 256>>>(x1, qpos, refp, so_w, so_b, aw_w, aw_b, value, S_h, S_l);

    // 10. apply vp_w per head: batched M=4000,N=32,K=256 (z = head) -> df planes
    bf_gemm<64,32,32,16><<<dim3(63,1,8),128,SMG32>>>(
        M4, 32, 256,
        S_h, S_l, 2048, 0, 256,
        vpw_h, vpw_l, Cd, 0, 32LL*Cd,
        nullptr, df_h, df_l, Cd, 0, 32,
        vp_b, 32, 1.f, 0, 8);

    // 11. deform output projection -> dproj fp32
    bf_gemm<64,128,32,32><<<dim3(63,2,1),256,SMG>>>(
        M4, 256, Cd,
        df_h, df_l, Cd, 0, 0,
        opw_h, opw_l, Cd, 0, 0,
        dproj, nullptr, nullptr, Cd, 0, 0,
        op_b, 0, 1.f, 0, 1);

    // 12. x2 = LN(x1 + dproj) (+ planes for FFN)
    add_ln_kernel<<<M4, 256>>>(x1, dproj, ln2_g, ln2_b, x2, x2_h, x2_l, 0);

    // 13. FFN1 (+ReLU) -> ffnh planes
    bf_gemm<64,128,32,32><<<dim3(63,4,1),256,SMG>>>(
        M4, FFNd, Cd,
        x2_h, x2_l, Cd, 0, 0,
        f1_h, f1_l, Cd, 0, 0,
        nullptr, fh_h, fh_l, FFNd, 0, 0,
        ffn_b1, 0, 1.f, 1, 1);

    // 14. FFN2 -> ffny fp32
    bf_gemm<64,128,32,32><<<dim3(63,2,1),256,SMG>>>(
        M4, 256, FFNd,
        fh_h, fh_l, FFNd, 0, 0,
        f2_h, f2_l, FFNd, 0, 0,
        ffny, nullptr, nullptr, Cd, 0, 0,
        ffn_b2, 0, 1.f, 0, 1);

    // 15. x3 = LN(x2 + ffn) -> out (transposed)
    add_ln_kernel<<<M4, 256>>>(x2, ffny, ln3_g, ln3_b, out, nullptr, nullptr, 1);
}

// round 14
// speedup vs baseline: 1.2346x; 1.0215x over previous
#include <cuda_runtime.h>
#include <cuda_bf16.h>
#include <math.h>
#include <stdint.h>

typedef __nv_bfloat16 bf16;

// ---------------- problem constants ----------------
#define NQd 1000
#define BSd 4
#define Cd 256
#define NHd 8
#define HDd 32
#define NVd 20000
#define Wb 100
#define Hb 200
#define FFNd 512
#define M4 4000            // BS*NQ
#define EPSd 1e-5f

// ---------------- scratch (single device symbol, partitioned on host) ----
__device__ __align__(256) float g_scratch[40000000];

// ================= helpers =========================
__device__ __forceinline__ uint32_t smem_u32(const void* p) {
    return (uint32_t)__cvta_generic_to_shared(p);
}
__device__ __forceinline__ void cp16(uint32_t s, const void* g, int sz) {
    asm volatile("cp.async.cg.shared.global [%0], [%1], 16, %2;\n"
                 :: "r"(s), "l"(g), "r"(sz));
}
__device__ __forceinline__ void mma16816(float* d, const uint32_t* a, const uint32_t* b) {
    asm volatile(
        "mma.sync.aligned.m16n8k16.row.col.f32.bf16.bf16.f32 "
        "{%0,%1,%2,%3}, {%4,%5,%6,%7}, {%8,%9}, {%0,%1,%2,%3};\n"
        : "+f"(d[0]), "+f"(d[1]), "+f"(d[2]), "+f"(d[3])
        : "r"(a[0]), "r"(a[1]), "r"(a[2]), "r"(a[3]), "r"(b[0]), "r"(b[1]));
}
__device__ __forceinline__ void ldsm_x4(uint32_t& r0, uint32_t& r1, uint32_t& r2, uint32_t& r3,
                                        uint32_t addr) {
    asm volatile("ldmatrix.sync.aligned.m8n8.x4.shared.b16 {%0,%1,%2,%3}, [%4];"
                 : "=r"(r0), "=r"(r1), "=r"(r2), "=r"(r3) : "r"(addr));
}
__device__ __forceinline__ void split_write(bf16* H, bf16* L, long long off, float x) {
    bf16 h = __float2bfloat16(x);
    H[off] = h;
    L[off] = __float2bfloat16(x - __bfloat162float(h));
}
__device__ __forceinline__ uint32_t pack_bf2(float a, float b) {
    __nv_bfloat162 t = __floats2bfloat162_rn(a, b);
    return *(uint32_t*)&t;
}

// ================= pipelined bf16x3 tensor-core GEMM =====================
// 3-stage cp.async ring, one __syncthreads per k-block, ldmatrix frag loads.
// MMA issue order: all hi*hi, then all hi*lo, then all lo*hi — consecutive
// MMAs on the same accumulator are >= 8 instructions apart (covers HMMA RAW).
template<int BM, int BN, int WM, int WN>
__global__ void __launch_bounds__((BM/WM)*(BN/WN)*32) bf_gemm(
    int M, int N, int K,
    const bf16* __restrict__ Ah, const bf16* __restrict__ Al, int sA,
    long long strA1, long long strA2,
    const bf16* __restrict__ Bh, const bf16* __restrict__ Bl, int sB,
    long long strB1, long long strB2,
    float* Cf, bf16* Ch, bf16* Cl, int ldc, long long strC1, long long strC2,
    const float* __restrict__ bias, int biasStr, float alpha, int relu, int batch2)
{
    constexpr int BK = 32;
    constexpr int NST = 3;
    constexpr int WARPS_M = BM / WM;
    constexpr int WARPS_N = BN / WN;
    constexpr int NT = WARPS_M * WARPS_N * 32;
    constexpr int LDA = 40;
    constexpr int MT = WM / 16;
    constexpr int NTn = WN / 8;
    constexpr int PA = BM * LDA;
    constexpr int PB = BN * LDA;
    constexpr int STAGE = 2 * PA + 2 * PB;
    constexpr int CA = BM * 4;
    constexpr int CT = (BM + BN) * 4;

    extern __shared__ __align__(16) bf16 sm[];

    int z = blockIdx.z;
    int i1 = z / batch2, i2 = z - i1 * batch2;
    Ah += i1 * strA1 + i2 * strA2;  Al += i1 * strA1 + i2 * strA2;
    Bh += i1 * strB1 + i2 * strB2;  Bl += i1 * strB1 + i2 * strB2;
    if (bias) bias += (long long)i2 * biasStr;
    long long coff = i1 * strC1 + i2 * strC2;

    int m0 = blockIdx.x * BM;
    int n0 = blockIdx.y * BN;
    int tid = threadIdx.x, lane = tid & 31, warp = tid >> 5;
    int wm = warp / WARPS_N, wn = warp - wm * WARPS_N;
    int lr = lane >> 2, lc = (lane & 3) << 1;

    uint32_t aoffB = (uint32_t)(((wm * WM + (lane & 15)) * LDA + ((lane >> 4) << 3)) * 2);
    uint32_t boffB = (uint32_t)(((wn * WN + (lane & 15)) * LDA + ((lane >> 4) << 3)) * 2);

    float acc[MT][NTn][4];
#pragma unroll
    for (int i = 0; i < MT; i++)
#pragma unroll
        for (int j = 0; j < NTn; j++)
#pragma unroll
            for (int c = 0; c < 4; c++) acc[i][j][c] = 0.f;

    int nkb = (K + BK - 1) / BK;

    auto load_stage = [&](int st, int k0) {
        bf16* basep = sm + st * STAGE;
        for (int c = tid; c < CT; c += NT) {
            if (c < CA) {
                int row = c >> 2, kc = (c & 3) << 3;
                int m = m0 + row, k = k0 + kc;
                int sz = 0;
                int mc = (m < M) ? m : (M - 1);
                int kcl = (k < K) ? k : 0;
                if (m < M && k < K) { sz = (K - k) * 2; if (sz > 16) sz = 16; }
                long long go = (long long)mc * sA + kcl;
                uint32_t s0 = smem_u32(basep + row * LDA + kc);
                cp16(s0, Ah + go, sz);
                cp16(s0 + PA * 2, Al + go, sz);
            } else {
                int cc = c - CA;
                int row = cc >> 2, kc = (cc & 3) << 3;
                int n = n0 + row, k = k0 + kc;
                int sz = 0;
                int nc = (n < N) ? n : (N - 1);
                int kcl = (k < K) ? k : 0;
                if (n < N && k < K) { sz = (K - k) * 2; if (sz > 16) sz = 16; }
                long long go = (long long)nc * sB + kcl;
                uint32_t s0 = smem_u32(basep + 2 * PA + row * LDA + kc);
                cp16(s0, Bh + go, sz);
                cp16(s0 + PB * 2, Bl + go, sz);
            }
        }
    };

    auto compute = [&](int st) {
        uint32_t base = smem_u32(sm + st * STAGE);
        uint32_t aAh = base + aoffB;
        uint32_t aAl = aAh + PA * 2;
        uint32_t aBh = base + 2 * PA * 2 + boffB;
        uint32_t aBl = aBh + PB * 2;
#pragma unroll
        for (int ks = 0; ks < BK; ks += 16) {
            uint32_t af[MT][4], afl[MT][4], bhf[NTn][2], blf[NTn][2];
#pragma unroll
            for (int i = 0; i < MT; i++)
                ldsm_x4(af[i][0], af[i][1], af[i][2], af[i][3],
                        aAh + (uint32_t)((i * 16 * LDA + ks) * 2));
#pragma unroll
            for (int i = 0; i < MT; i++)
                ldsm_x4(afl[i][0], afl[i][1], afl[i][2], afl[i][3],
                        aAl + (uint32_t)((i * 16 * LDA + ks) * 2));
#pragma unroll
            for (int pr = 0; pr < NTn / 2; pr++) {
                uint32_t t0, t1, t2, t3;
                ldsm_x4(t0, t1, t2, t3, aBh + (uint32_t)((pr * 16 * LDA + ks) * 2));
                bhf[2*pr][0] = t0; bhf[2*pr+1][0] = t1;
                bhf[2*pr][1] = t2; bhf[2*pr+1][1] = t3;
                ldsm_x4(t0, t1, t2, t3, aBl + (uint32_t)((pr * 16 * LDA + ks) * 2));
                blf[2*pr][0] = t0; blf[2*pr+1][0] = t1;
                blf[2*pr][1] = t2; blf[2*pr+1][1] = t3;
            }
            // independent MMA bursts: same-acc MMAs separated by 8 instructions
#pragma unroll
            for (int i = 0; i < MT; i++)
#pragma unroll
                for (int j = 0; j < NTn; j++)
                    mma16816(acc[i][j], af[i], bhf[j]);   // hi*hi
#pragma unroll
            for (int i = 0; i < MT; i++)
#pragma unroll
                for (int j = 0; j < NTn; j++)
                    mma16816(acc[i][j], af[i], blf[j]);   // hi*lo
#pragma unroll
            for (int i = 0; i < MT; i++)
#pragma unroll
                for (int j = 0; j < NTn; j++)
                    mma16816(acc[i][j], afl[i], bhf[j]);  // lo*hi
        }
    };

    load_stage(0, 0);
    asm volatile("cp.async.commit_group;\n");
    if (nkb > 1) {
        load_stage(1, BK);
        asm volatile("cp.async.commit_group;\n");
    }
    for (int kb = 0; kb < nkb; kb++) {
        if (kb + 1 < nkb) asm volatile("cp.async.wait_group 1;\n");
        else              asm volatile("cp.async.wait_group 0;\n");
        __syncthreads();
        compute(kb % NST);
        if (kb + 2 < nkb) {
            load_stage((kb + 2) % NST, (kb + 2) * BK);
            asm volatile("cp.async.commit_group;\n");
        }
    }

    float* Cfp = Cf ? Cf + coff : nullptr;
    bf16* Chp = Ch ? Ch + coff : nullptr;
    bf16* Clp = Cl ? Cl + coff : nullptr;
#pragma unroll
    for (int i = 0; i < MT; i++) {
        int row0 = m0 + wm * WM + i * 16 + lr;
#pragma unroll
        for (int j = 0; j < NTn; j++) {
            int col0 = n0 + wn * WN + j * 8 + lc;
#pragma unroll
            for (int c = 0; c < 4; c++) {
                int m = row0 + ((c >> 1) << 3);
                int n = col0 + (c & 1);
                if (m < M && n < N) {
                    float vv = acc[i][j][c] * alpha;
                    if (bias) vv += bias[n];
                    if (relu) vv = fmaxf(vv, 0.f);
                    long long o = (long long)m * ldc + n;
                    if (Cfp) Cfp[o] = vv;
                    if (Chp) {
                        bf16 hh = __float2bfloat16(vv);
                        Chp[o] = hh;
                        Clp[o] = __float2bfloat16(vv - __bfloat162float(hh));
                    }
                }
            }
        }
    }
}

// ================= flash attention (bf16x3, online softmax, ldmatrix) ====
__global__ void __launch_bounds__(256) flash_kernel(
    const bf16* __restrict__ qkvh, const bf16* __restrict__ qkvl,
    const bf16* __restrict__ vTh,  const bf16* __restrict__ vTl,
    bf16* __restrict__ aoh, bf16* __restrict__ aol)
{
    constexpr int LKV = 64;
    constexpr int LDQ = 40, LDV = 72;
    constexpr int QPA = 128 * LDQ;
    constexpr int KPA = LKV * LDQ;
    constexpr int VPA = 32 * LDV;
    constexpr int KVSTAGE = 2 * KPA + 2 * VPA;

    extern __shared__ __align__(16) bf16 smf[];
    bf16* Qh = smf;
    bf16* Ql = smf + QPA;
    bf16* STG = smf + 2 * QPA;

    int bz = blockIdx.y;
    int b = bz >> 3, h = bz & 7;
    int q0 = blockIdx.x * 128;
    int tid = threadIdx.x, lane = tid & 31, w = tid >> 5;
    int lr = lane >> 2, lc = (lane & 3) << 1;

    uint32_t qoffB = (uint32_t)(((w * 16 + (lane & 15)) * LDQ + ((lane >> 4) << 3)) * 2);
    uint32_t koffB = (uint32_t)(((lane & 15) * LDQ + ((lane >> 4) << 3)) * 2);
    uint32_t voffB = (uint32_t)(((lane & 15) * LDV + ((lane >> 4) << 3)) * 2);

    const bf16* qbase_h = qkvh + (long long)b * NQd * 768 + h * 32;
    const bf16* qbase_l = qkvl + (long long)b * NQd * 768 + h * 32;
    const bf16* vbase_h = vTh + (long long)bz * (HDd * NQd);
    const bf16* vbase_l = vTl + (long long)bz * (HDd * NQd);

    for (int c = tid; c < 1024; c += 256) {
        int plane = c >> 9, rem = c & 511;
        int row = rem >> 2, kc = (rem & 3) << 3;
        int q = q0 + row;
        int qm = (q < NQd) ? q : (NQd - 1);
        int sz = (q < NQd) ? 16 : 0;
        const bf16* src = (plane ? qbase_l : qbase_h) + (long long)qm * 768 + kc;
        uint32_t dst = smem_u32((plane ? Ql : Qh) + row * LDQ + kc);
        cp16(dst, src, sz);
    }

    auto load_kv = [&](int st, int kv0) {
        bf16* Kh = STG + st * KVSTAGE;
        bf16* Kl = Kh + KPA;
        bf16* Vh = Kl + KPA;
        bf16* Vl = Vh + VPA;
        for (int c = tid; c < 512; c += 256) {
            int plane = c >> 8, rem = c & 255;
            int row = rem >> 2, kc = (rem & 3) << 3;
            int kv = kv0 + row;
            int kvm = (kv < NQd) ? kv : (NQd - 1);
            int sz = (kv < NQd) ? 16 : 0;
            const bf16* src = (plane ? qbase_l : qbase_h) + (long long)kvm * 768 + 256 + kc;
            uint32_t dst = smem_u32((plane ? Kl : Kh) + row * LDQ + kc);
            cp16(dst, src, sz);
        }
        for (int c = tid; c < 512; c += 256) {
            int plane = c >> 8, rem = c & 255;
            int d = rem >> 3, cc = (rem & 7) << 3;
            int col = kv0 + cc;
            int colm = (col < NQd) ? col : (NQd - 8);
            int sz = (NQd - col) * 2;
            if (sz < 0) sz = 0; if (sz > 16) sz = 16;
            const bf16* src = (plane ? vbase_l : vbase_h) + (long long)d * NQd + colm;
            uint32_t dst = smem_u32((plane ? Vl : Vh) + d * LDV + cc);
            cp16(dst, src, sz);
        }
    };

    load_kv(0, 0);
    asm volatile("cp.async.commit_group;\n");

    uint32_t qfh[2][4], qfl[2][4];
    float o[4][4];
    float m0 = -1e30f, m1 = -1e30f, l0 = 0.f, l1 = 0.f;
#pragma unroll
    for (int jn = 0; jn < 4; jn++)
#pragma unroll
        for (int c = 0; c < 4; c++) o[jn][c] = 0.f;

    const float alpha = 0.17677669529663687f;
    constexpr int NKV = 16;

    for (int kb = 0; kb < NKV; kb++) {
        if (kb + 1 < NKV) {
            load_kv((kb + 1) & 1, (kb + 1) * LKV);
            asm volatile("cp.async.commit_group;\n");
            asm volatile("cp.async.wait_group 1;\n");
        } else {
            asm volatile("cp.async.wait_group 0;\n");
        }
        __syncthreads();

        if (kb == 0) {
            uint32_t qh0 = smem_u32(Qh) + qoffB;
            uint32_t ql0 = smem_u32(Ql) + qoffB;
#pragma unroll
            for (int t = 0; t < 2; t++) {
                ldsm_x4(qfh[t][0], qfh[t][1], qfh[t][2], qfh[t][3], qh0 + t * 32);
                ldsm_x4(qfl[t][0], qfl[t][1], qfl[t][2], qfl[t][3], ql0 + t * 32);
            }
        }

        int st = kb & 1;
        int kv0 = kb * LKV;
        bf16* Kh = STG + st * KVSTAGE;
        bf16* Kl = Kh + KPA;
        bf16* Vh = Kl + KPA;
        bf16* Vl = Vh + VPA;
        uint32_t kh0 = smem_u32(Kh) + koffB;
        uint32_t kl0 = smem_u32(Kl) + koffB;
        uint32_t vh0 = smem_u32(Vh) + voffB;
        uint32_t vl0 = smem_u32(Vl) + voffB;

        float sa[8][4];
#pragma unroll
        for (int j = 0; j < 8; j++)
#pragma unroll
            for (int c = 0; c < 4; c++) sa[j][c] = 0.f;

#pragma unroll
        for (int t = 0; t < 2; t++) {
            int ks = t * 16;
            uint32_t bh[8][2], bl[8][2];
#pragma unroll
            for (int pr = 0; pr < 4; pr++) {
                uint32_t t0, t1, t2, t3;
                ldsm_x4(t0, t1, t2, t3, kh0 + (uint32_t)((pr * 16 * LDQ + ks) * 2));
                bh[2*pr][0] = t0; bh[2*pr+1][0] = t1;
                bh[2*pr][1] = t2; bh[2*pr+1][1] = t3;
                ldsm_x4(t0, t1, t2, t3, kl0 + (uint32_t)((pr * 16 * LDQ + ks) * 2));
                bl[2*pr][0] = t0; bl[2*pr+1][0] = t1;
                bl[2*pr][1] = t2; bl[2*pr+1][1] = t3;
            }
            // split bursts: same-sa MMAs 8 instructions apart
#pragma unroll
            for (int j = 0; j < 8; j++) mma16816(sa[j], qfh[t], bh[j]);
#pragma unroll
            for (int j = 0; j < 8; j++) mma16816(sa[j], qfh[t], bl[j]);
#pragma unroll
            for (int j = 0; j < 8; j++) mma16816(sa[j], qfl[t], bh[j]);
        }

#pragma unroll
        for (int j = 0; j < 8; j++)
#pragma unroll
            for (int c = 0; c < 4; c++) sa[j][c] *= alpha;
        if (kv0 + LKV > NQd) {
#pragma unroll
            for (int j = 0; j < 8; j++) {
                int cb = kv0 + 8 * j + lc;
                if (cb     >= NQd) { sa[j][0] = -1e30f; sa[j][2] = -1e30f; }
                if (cb + 1 >= NQd) { sa[j][1] = -1e30f; sa[j][3] = -1e30f; }
            }
        }

        float mx0 = -1e30f, mx1 = -1e30f;
#pragma unroll
        for (int j = 0; j < 8; j++) {
            mx0 = fmaxf(mx0, fmaxf(sa[j][0], sa[j][1]));
            mx1 = fmaxf(mx1, fmaxf(sa[j][2], sa[j][3]));
        }
        mx0 = fmaxf(mx0, __shfl_xor_sync(0xffffffffu, mx0, 1));
        mx0 = fmaxf(mx0, __shfl_xor_sync(0xffffffffu, mx0, 2));
        mx1 = fmaxf(mx1, __shfl_xor_sync(0xffffffffu, mx1, 1));
        mx1 = fmaxf(mx1, __shfl_xor_sync(0xffffffffu, mx1, 2));
        float mn0 = fmaxf(m0, mx0), mn1 = fmaxf(m1, mx1);
        float sc0 = __expf(m0 - mn0), sc1 = __expf(m1 - mn1);
        m0 = mn0; m1 = mn1;

        float su0 = 0.f, su1 = 0.f;
#pragma unroll
        for (int j = 0; j < 8; j++) {
            sa[j][0] = __expf(sa[j][0] - mn0);
            sa[j][1] = __expf(sa[j][1] - mn0);
            sa[j][2] = __expf(sa[j][2] - mn1);
            sa[j][3] = __expf(sa[j][3] - mn1);
            su0 += sa[j][0] + sa[j][1];
            su1 += sa[j][2] + sa[j][3];
        }
        su0 += __shfl_xor_sync(0xffffffffu, su0, 1);
        su0 += __shfl_xor_sync(0xffffffffu, su0, 2);
        su1 += __shfl_xor_sync(0xffffffffu, su1, 1);
        su1 += __shfl_xor_sync(0xffffffffu, su1, 2);
        l0 = l0 * sc0 + su0;
        l1 = l1 * sc1 + su1;

#pragma unroll
        for (int jn = 0; jn < 4; jn++) {
            o[jn][0] *= sc0; o[jn][1] *= sc0;
            o[jn][2] *= sc1; o[jn][3] *= sc1;
        }

#pragma unroll
        for (int t = 0; t < 4; t++) {
            int j0 = 2 * t, j1 = 2 * t + 1;
            uint32_t aph[4], apl[4];
            {
                float v00 = sa[j0][0], v01 = sa[j0][1], v02 = sa[j0][2], v03 = sa[j0][3];
                float v10 = sa[j1][0], v11 = sa[j1][1], v12 = sa[j1][2], v13 = sa[j1][3];
                bf16 h00 = __float2bfloat16(v00), h01 = __float2bfloat16(v01);
                bf16 h02 = __float2bfloat16(v02), h03 = __float2bfloat16(v03);
                bf16 h10 = __float2bfloat16(v10), h11 = __float2bfloat16(v11);
                bf16 h12 = __float2bfloat16(v12), h13 = __float2bfloat16(v13);
                aph[0] = ((uint32_t)*(uint16_t*)&h00) | ((uint32_t)*(uint16_t*)&h01 << 16);
                aph[1] = ((uint32_t)*(uint16_t*)&h02) | ((uint32_t)*(uint16_t*)&h03 << 16);
                aph[2] = ((uint32_t)*(uint16_t*)&h10) | ((uint32_t)*(uint16_t*)&h11 << 16);
                aph[3] = ((uint32_t)*(uint16_t*)&h12) | ((uint32_t)*(uint16_t*)&h13 << 16);
                apl[0] = pack_bf2(v00 - __bfloat162float(h00), v01 - __bfloat162float(h01));
                apl[1] = pack_bf2(v02 - __bfloat162float(h02), v03 - __bfloat162float(h03));
                apl[2] = pack_bf2(v10 - __bfloat162float(h10), v11 - __bfloat162float(h11));
                apl[3] = pack_bf2(v12 - __bfloat162float(h12), v13 - __bfloat162float(h13));
            }
            int ks = t * 16;
            uint32_t bvh[4][2], bvl[4][2];
#pragma unroll
            for (int pr = 0; pr < 2; pr++) {
                uint32_t t0, t1, t2, t3;
                ldsm_x4(t0, t1, t2, t3, vh0 + (uint32_t)((pr * 16 * LDV + ks) * 2));
                bvh[2*pr][0] = t0; bvh[2*pr+1][0] = t1;
                bvh[2*pr][1] = t2; bvh[2*pr+1][1] = t3;
                ldsm_x4(t0, t1, t2, t3, vl0 + (uint32_t)((pr * 16 * LDV + ks) * 2));
                bvl[2*pr][0] = t0; bvl[2*pr+1][0] = t1;
                bvl[2*pr][1] = t2; bvl[2*pr+1][1] = t3;
            }
            // split bursts: same-o MMAs 4 instructions apart
#pragma unroll
            for (int jn = 0; jn < 4; jn++) mma16816(o[jn], aph, bvh[jn]);
#pragma unroll
            for (int jn = 0; jn < 4; jn++) mma16816(o[jn], aph, bvl[jn]);
#pragma unroll
            for (int jn = 0; jn < 4; jn++) mma16816(o[jn], apl, bvh[jn]);
        }
        __syncthreads();
    }

    float il0 = 1.f / l0, il1 = 1.f / l1;
    int qa = q0 + w * 16 + lr;
    int qb = qa + 8;
#pragma unroll
    for (int jn = 0; jn < 4; jn++) {
        int d = jn * 8 + lc;
        if (qa < NQd) {
            long long oa = ((long long)b * NQd + qa) * Cd + h * 32 + d;
            split_write(aoh, aol, oa,     o[jn][0] * il0);
            split_write(aoh, aol, oa + 1, o[jn][1] * il0);
        }
        if (qb < NQd) {
            long long ob = ((long long)b * NQd + qb) * Cd + h * 32 + d;
            split_write(aoh, aol, ob,     o[jn][2] * il1);
            split_write(aoh, aol, ob + 1, o[jn][3] * il1);
        }
    }
}

// ---------------- prep: transpose query / add pos + split ----------------
__global__ void prep0_kernel(const float* __restrict__ query,
                             const float* __restrict__ qpos,
                             float* __restrict__ xq,
                             bf16* __restrict__ xq_h, bf16* __restrict__ xq_l,
                             bf16* __restrict__ qk_h, bf16* __restrict__ qk_l)
{
    int r = blockIdx.x, t = threadIdx.x;
    int b = r / NQd, q = r - b * NQd;
    long long src = ((long long)q * BSd + b) * Cd + t;
    long long dst = (long long)r * Cd + t;
    float x = query[src];
    float qp = qpos[src];
    xq[dst] = x;
    split_write(xq_h, xq_l, dst, x);
    split_write(qk_h, qk_l, dst, x + qp);
}

// ---------------- merged weight splits ----------------
struct SplitJob { const float* s; bf16* h; bf16* l; int n; };
struct SplitJobs6 { SplitJob j[6]; };
__global__ void split_multi_kernel(SplitJobs6 jobs)
{
    SplitJob jb = jobs.j[blockIdx.y];
    for (int i = blockIdx.x * 256 + threadIdx.x; i < jb.n; i += gridDim.x * 256)
        split_write(jb.h, jb.l, i, jb.s[i]);
}

// ---------------- vh transpose: qkv v-section -> vT[b,h][d][q] ----------
__global__ void vtrans_kernel(const bf16* __restrict__ qh, const bf16* __restrict__ ql,
                              bf16* __restrict__ th, bf16* __restrict__ tl)
{
    __shared__ bf16 tile_h[32][33];
    __shared__ bf16 tile_l[32][33];
    int q0 = blockIdx.x * 32, h = blockIdx.y, b = blockIdx.z;
    int tx = threadIdx.x, ty = threadIdx.y;
    for (int i = ty; i < 32; i += 8) {
        int q = q0 + i;
        bf16 vh = __float2bfloat16(0.f), vl = __float2bfloat16(0.f);
        if (q < NQd) {
            long long o = ((long long)(b * NQd + q)) * 768 + 512 + h * 32 + tx;
            vh = qh[o]; vl = ql[o];
        }
        tile_h[i][tx] = vh; tile_l[i][tx] = vl;
    }
    __syncthreads();
    for (int i = ty; i < 32; i += 8) {
        int d = i, q = q0 + tx;
        if (q < NQd) {
            long long o = ((long long)(b * NHd + h)) * (HDd * NQd) + (long long)d * NQd + q;
            th[o] = tile_h[tx][d];
            tl[o] = tile_l[tx][d];
        }
    }
}

// ---------------- residual + LayerNorm (+ optional split planes) --------
__global__ void add_ln_kernel(const float* __restrict__ a,
                              const float* __restrict__ r2,
                              const float* __restrict__ g,
                              const float* __restrict__ be,
                              float* __restrict__ out,
                              bf16* __restrict__ oh, bf16* __restrict__ ol,
                              int transpose_out)
{
    int r = blockIdx.x, t = threadIdx.x;
    __shared__ float sh[9];
    float v = a[(long long)r * Cd + t] + r2[(long long)r * Cd + t];

    float s = v;
#pragma unroll
    for (int o = 16; o; o >>= 1) s += __shfl_xor_sync(0xffffffffu, s, o);
    if ((t & 31) == 0) sh[t >> 5] = s;
    __syncthreads();
    if (t == 0) {
        float x = 0.f;
        for (int i = 0; i < 8; i++) x += sh[i];
        sh[8] = x * (1.f / Cd);
    }
    __syncthreads();
    float mean = sh[8];
    float d = v - mean;
    float s2 = d * d;
#pragma unroll
    for (int o = 16; o; o >>= 1) s2 += __shfl_xor_sync(0xffffffffu, s2, o);
    if ((t & 31) == 0) sh[t >> 5] = s2;
    __syncthreads();
    if (t == 0) {
        float x = 0.f;
        for (int i = 0; i < 8; i++) x += sh[i];
        sh[8] = rsqrtf(x * (1.f / Cd) + EPSd);
    }
    __syncthreads();
    float y = d * sh[8] * g[t] + be[t];

    long long oi;
    if (transpose_out) {
        int b = r / NQd, q = r - b * NQd;
        oi = ((long long)q * BSd + b) * Cd + t;
    } else {
        oi = (long long)r * Cd + t;
    }
    if (out) out[oi] = y;
    if (oh) split_write(oh, ol, (long long)r * Cd + t, y);
}

// ---------------- fused deformable sampling on RAW value (float4) -------
// out[b,q,h,:] = (sum_{p,corner} w * value_raw[idx]) @ vp_w[hslice]^T
// S[b,q][h*256+c] = weighted raw sum (fp32 exact) -> hi/lo planes.
// thread layout: worker = t/64 handles heads {worker, worker+4};
// cl = (t%64)*4 -> float4 channel group.
__global__ void deform_kernel(const float* __restrict__ x1,
                              const float* __restrict__ qpos,
                              const float* __restrict__ refp,
                              const float* __restrict__ so_w, const float* __restrict__ so_b,
                              const float* __restrict__ aw_w, const float* __restrict__ aw_b,
                              const float* __restrict__ value,
                              bf16* __restrict__ Shp, bf16* __restrict__ Slp)
{
    int r = blockIdx.x, t = threadIdx.x;
    int b = r / NQd, q = r - b * NQd;

    __shared__ float qrow[Cd];
    __shared__ float offb[64];
    __shared__ float awb[32];
    __shared__ int x0s[32];
    __shared__ int y0s[32];
    __shared__ float lxs[32];
    __shared__ float lys[32];

    qrow[t] = x1[(long long)r * Cd + t] + qpos[((long long)q * BSd + b) * Cd + t];
    __syncthreads();

    if (t < 64) {
        float s = so_b[t];
        const float* wrow = so_w + t * Cd;
#pragma unroll 8
        for (int c = 0; c < Cd; c++) s = fmaf(qrow[c], wrow[c], s);
        offb[t] = s;
    } else if (t < 96) {
        int j = t - 64;
        float s = aw_b[j];
        const float* wrow = aw_w + j * Cd;
#pragma unroll 8
        for (int c = 0; c < Cd; c++) s = fmaf(qrow[c], wrow[c], s);
        awb[j] = s;
    }
    __syncthreads();

    if (t < NHd) {
        float a0 = awb[t * 4 + 0], a1 = awb[t * 4 + 1], a2 = awb[t * 4 + 2], a3 = awb[t * 4 + 3];
        float m = fmaxf(fmaxf(a0, a1), fmaxf(a2, a3));
        float e0 = expf(a0 - m), e1 = expf(a1 - m), e2 = expf(a2 - m), e3 = expf(a3 - m);
        float inv = 1.f / (e0 + e1 + e2 + e3);
        awb[t * 4 + 0] = e0 * inv;
        awb[t * 4 + 1] = e1 * inv;
        awb[t * 4 + 2] = e2 * inv;
        awb[t * 4 + 3] = e3 * inv;
    }
    if (t < 32) {
        float rx = refp[((long long)b * NQd + q) * 2 + 0];
        float ry = refp[((long long)b * NQd + q) * 2 + 1];
        float lx = rx + offb[t * 2 + 0] * (1.f / Wb);
        float ly = ry + offb[t * 2 + 1] * (1.f / Hb);
        float xim = lx * Wb - 0.5f;
        float yim = ly * Hb - 0.5f;
        float x0f = floorf(xim), y0f = floorf(yim);
        x0s[t] = (int)x0f;
        y0s[t] = (int)y0f;
        lxs[t] = xim - x0f;
        lys[t] = yim - y0f;
    }
    __syncthreads();

    // float4 gather: 4 workers x 64 channel-groups
    int worker = t >> 6;            // 0..3
    int cl = (t & 63) << 2;         // channel group base (0,4,...,252)
    const float* vbase = value + (long long)b * Cd + cl;   // + n*(BSd*Cd)
#pragma unroll
    for (int hh = 0; hh < 2; hh++) {
        int h = worker + hh * 4;
        float4 s = make_float4(0.f, 0.f, 0.f, 0.f);
#pragma unroll
        for (int p = 0; p < 4; p++) {
            int hp = h * 4 + p;
            int x0 = x0s[hp], y0 = y0s[hp];
            float lx = lxs[hp], ly = lys[hp];
            float aw = awb[hp];
#pragma unroll
            for (int dy = 0; dy < 2; dy++)
#pragma unroll
                for (int dx = 0; dx < 2; dx++) {
                    int xi = x0 + dx, yi = y0 + dy;
                    if (xi >= 0 && xi < Wb && yi >= 0 && yi < Hb) {
                        float wgt = aw * (dx ? lx : 1.f - lx) * (dy ? ly : 1.f - ly);
                        const float4 vv = *(const float4*)(vbase +
                            (long long)(yi * Wb + xi) * (BSd * Cd));
                        s.x = fmaf(wgt, vv.x, s.x);
                        s.y = fmaf(wgt, vv.y, s.y);
                        s.z = fmaf(wgt, vv.z, s.z);
                        s.w = fmaf(wgt, vv.w, s.w);
                    }
                }
        }
        long long o = (long long)r * 2048 + h * 256 + cl;
        split_write(Shp, Slp, o + 0, s.x);
        split_write(Shp, Slp, o + 1, s.y);
        split_write(Shp, Slp, o + 2, s.z);
        split_write(Shp, Slp, o + 3, s.w);
    }
}

// ---------------- launcher ----------------
static inline int cdiv(int a, int b) { return (a + b - 1) / b; }

extern "C" void kernel_launch(void* const* d_in, const int* in_sizes, int n_in,
                              void* d_out, int out_size)
{
    (void)in_sizes; (void)n_in; (void)out_size;
    const float* query  = (const float*)d_in[0];
    const float* value  = (const float*)d_in[1];
    const float* qpos   = (const float*)d_in[2];
    const float* refp   = (const float*)d_in[3];
    const float* in_w   = (const float*)d_in[6];
    const float* in_b   = (const float*)d_in[7];
    const float* mha_ow = (const float*)d_in[8];
    const float* mha_ob = (const float*)d_in[9];
    const float* so_w   = (const float*)d_in[10];
    const float* so_b   = (const float*)d_in[11];
    const float* aw_w   = (const float*)d_in[12];
    const float* aw_b   = (const float*)d_in[13];
    const float* vp_w   = (const float*)d_in[14];
    const float* vp_b   = (const float*)d_in[15];
    const float* op_w   = (const float*)d_in[16];
    const float* op_b   = (const float*)d_in[17];
    const float* ffn_w1 = (const float*)d_in[18];
    const float* ffn_b1 = (const float*)d_in[19];
    const float* ffn_w2 = (const float*)d_in[20];
    const float* ffn_b2 = (const float*)d_in[21];
    const float* ln1_g  = (const float*)d_in[22];
    const float* ln1_b  = (const float*)d_in[23];
    const float* ln2_g  = (const float*)d_in[24];
    const float* ln2_b  = (const float*)d_in[25];
    const float* ln3_g  = (const float*)d_in[26];
    const float* ln3_b  = (const float*)d_in[27];
    float* out = (float*)d_out;

    float* base = nullptr;
    cudaGetSymbolAddress((void**)&base, g_scratch);
    float* p = base;
    auto takeF = [&](long long n) { float* r = p; p += n; return r; };
    auto takeB = [&](long long n) { bf16* r = (bf16*)p; p += (n + 1) / 2; return r; };

    float* xq     = takeF(1024000);
    bf16* xq_h    = takeB(1024000);
    bf16* xq_l    = takeB(1024000);
    bf16* qk_h    = takeB(1024000);
    bf16* qk_l    = takeB(1024000);
    bf16* w_in_h  = takeB(196608);
    bf16* w_in_l  = takeB(196608);
    bf16* ow_h    = takeB(65536);
    bf16* ow_l    = takeB(65536);
    bf16* vpw_h   = takeB(65536);
    bf16* vpw_l   = takeB(65536);
    bf16* opw_h   = takeB(65536);
    bf16* opw_l   = takeB(65536);
    bf16* f1_h    = takeB(131072);
    bf16* f1_l    = takeB(131072);
    bf16* f2_h    = takeB(131072);
    bf16* f2_l    = takeB(131072);
    bf16* qkv_h   = takeB(3072000);
    bf16* qkv_l   = takeB(3072000);
    bf16* vT_h    = takeB(1024000);
    bf16* vT_l    = takeB(1024000);
    bf16* ao_h    = takeB(1024000);
    bf16* ao_l    = takeB(1024000);
    float* mha    = takeF(1024000);
    float* x1     = takeF(1024000);
    bf16* S_h     = takeB(8192000);   // [b,q][h*256+c]
    bf16* S_l     = takeB(8192000);
    bf16* df_h    = takeB(1024000);
    bf16* df_l    = takeB(1024000);
    float* dproj  = takeF(1024000);
    float* x2     = takeF(1024000);
    bf16* x2_h    = takeB(1024000);
    bf16* x2_l    = takeB(1024000);
    bf16* fh_h    = takeB(2048000);
    bf16* fh_l    = takeB(2048000);
    float* ffny   = takeF(1024000);

    // 64x128 tile, 3 stages: stage = 2*(64+128)*40 bf16 = 30720 B, x3 = 92160 B
    const int SMG = 92160;
    // 64x32 tile, 3 stages: stage = 2*(64+32)*40 bf16 = 15360 B, x3 = 46080 B
    const int SMG32 = 46080;
    cudaFuncSetAttribute(bf_gemm<64,128,32,32>, cudaFuncAttributeMaxDynamicSharedMemorySize, SMG);
    cudaFuncSetAttribute(bf_gemm<64,32,32,16>,  cudaFuncAttributeMaxDynamicSharedMemorySize, SMG32);
    cudaFuncSetAttribute(flash_kernel, cudaFuncAttributeMaxDynamicSharedMemorySize, 61440);

    // 1. prep
    prep0_kernel<<<M4, 256>>>(query, qpos, xq, xq_h, xq_l, qk_h, qk_l);

    // 2. weight splits (one launch)
    SplitJobs6 jobs;
    jobs.j[0] = { in_w,   w_in_h, w_in_l, 196608 };
    jobs.j[1] = { mha_ow, ow_h,   ow_l,   65536 };
    jobs.j[2] = { vp_w,   vpw_h,  vpw_l,  65536 };
    jobs.j[3] = { op_w,   opw_h,  opw_l,  65536 };
    jobs.j[4] = { ffn_w1, f1_h,   f1_l,   131072 };
    jobs.j[5] = { ffn_w2, f2_h,   f2_l,   131072 };
    split_multi_kernel<<<dim3(96, 6), 256>>>(jobs);

    // 3. QK projection -> qkv planes cols [0,512)
    bf_gemm<64,128,32,32><<<dim3(63,4,1),256,SMG>>>(
        M4, 512, Cd,
        qk_h, qk_l, Cd, 0, 0,
        w_in_h, w_in_l, Cd, 0, 0,
        nullptr, qkv_h, qkv_l, 768, 0, 0,
        in_b, 0, 1.f, 0, 1);

    // 4. V projection -> qkv planes cols [512,768)
    bf_gemm<64,128,32,32><<<dim3(63,2,1),256,SMG>>>(
        M4, 256, Cd,
        xq_h, xq_l, Cd, 0, 0,
        w_in_h + 512*Cd, w_in_l + 512*Cd, Cd, 0, 0,
        nullptr, qkv_h + 512, qkv_l + 512, 768, 0, 0,
        in_b + 512, 0, 1.f, 0, 1);

    // 5. vh transpose -> vT[b,h][d][q]
    vtrans_kernel<<<dim3(32, NHd, BSd), dim3(32,8)>>>(qkv_h, qkv_l, vT_h, vT_l);

    // 6. flash attention -> ao planes
    flash_kernel<<<dim3(8, 32), 256, 61440>>>(qkv_h, qkv_l, vT_h, vT_l, ao_h, ao_l);

    // 7. MHA output projection -> mha fp32
    bf_gemm<64,128,32,32><<<dim3(63,2,1),256,SMG>>>(
        M4, 256, Cd,
        ao_h, ao_l, Cd, 0, 0,
        ow_h, ow_l, Cd, 0, 0,
        mha, nullptr, nullptr, Cd, 0, 0,
        mha_ob, 0, 1.f, 0, 1);

    // 8. x1 = LN(x + mha)
    add_ln_kernel<<<M4, 256>>>(xq, mha, ln1_g, ln1_b, x1, nullptr, nullptr, 0);

    // 9. deformable sampling on RAW value -> S planes [b,q][h*256+c]
    deform_kernel<<<M4, 256>>>(x1, qpos, refp, so_w, so_b, aw_w, aw_b, value, S_h, S_l);

    // 10. apply vp_w per head: batched M=4000,N=32,K=256 (z = head) -> df planes
    bf_gemm<64,32,32,16><<<dim3(63,1,8),128,SMG32>>>(
        M4, 32, 256,
        S_h, S_l, 2048, 0, 256,
        vpw_h, vpw_l, Cd, 0, 32LL*Cd,
        nullptr, df_h, df_l, Cd, 0, 32,
        vp_b, 32, 1.f, 0, 8);

    // 11. deform output projection -> dproj fp32
    bf_gemm<64,128,32,32><<<dim3(63,2,1),256,SMG>>>(
        M4, 256, Cd,
        df_h, df_l, Cd, 0, 0,
        opw_h, opw_l, Cd, 0, 0,
        dproj, nullptr, nullptr, Cd, 0, 0,
        op_b, 0, 1.f, 0, 1);

    // 12. x2 = LN(x1 + dproj) (+ planes for FFN)
    add_ln_kernel<<<M4, 256>>>(x1, dproj, ln2_g, ln2_b, x2, x2_h, x2_l, 0);

    // 13. FFN1 (+ReLU) -> ffnh planes
    bf_gemm<64,128,32,32><<<dim3(63,4,1),256,SMG>>>(
        M4, FFNd, Cd,
        x2_h, x2_l, Cd, 0, 0,
        f1_h, f1_l, Cd, 0, 0,
        nullptr, fh_h, fh_l, FFNd, 0, 0,
        ffn_b1, 0, 1.f, 1, 1);

    // 14. FFN2 -> ffny fp32
    bf_gemm<64,128,32,32><<<dim3(63,2,1),256,SMG>>>(
        M4, 256, FFNd,
        fh_h, fh_l, FFNd, 0, 0,
        f2_h, f2_l, FFNd, 0, 0,
        ffny, nullptr, nullptr, Cd, 0, 0,
        ffn_b2, 0, 1.f, 0, 1);

    // 15. x3 = LN(x2 + ffn) -> out (transposed)
    add_ln_kernel<<<M4, 256>>>(x2, ffny, ln3_g, ln3_b, out, nullptr, nullptr, 1);
}